// round 3
// baseline (speedup 1.0000x reference)
#include <cuda_runtime.h>
#include <cuda_bf16.h>

#define Bx 16
#define Nx 4096
#define Sx 1024
#define Kx 32
#define Dx 64
#define Px (Bx*Sx*Kx)   // 524288

typedef unsigned long long ull;

// ---------------- device scratch (static, no allocation) ----------------
__device__ float g_centers[Bx*Sx*3];
__device__ int   g_gidx[Bx*Sx*Kx];
__device__ float g_ptsT[Bx*Nx*Dx];
__device__ float g_Y1[64u*Px];
__device__ float g_Y2[64u*Px];
__device__ float g_Y3[128u*Px];
__device__ float g_sum[384];
__device__ float g_sq[384];
__device__ float g_a[384];    // BN scale A = gamma*rsqrt(var+eps)
__device__ float g_bb[384];   // BN offset B = beta - mu*A

// ---------------- f32x2 helpers ----------------
__device__ __forceinline__ void ffma2(ull &acc, ull a, ull b) {
    asm("fma.rn.f32x2 %0, %1, %2, %0;" : "+l"(acc) : "l"(a), "l"(b));
}
__device__ __forceinline__ ull packf2(float lo, float hi) {
    ull r; asm("mov.b64 %0, {%1, %2};" : "=l"(r) : "f"(lo), "f"(hi)); return r;
}
__device__ __forceinline__ float2 unpackf2(ull v) {
    float lo, hi; asm("mov.b64 {%0, %1}, %2;" : "=f"(lo), "=f"(hi) : "l"(v));
    return make_float2(lo, hi);
}

// ---------------- zero stats ----------------
__global__ void zero_stats_kernel() {
    int t = blockIdx.x*256 + threadIdx.x;
    if (t < 384) { g_sum[t] = 0.f; g_sq[t] = 0.f; }
}

// ---------------- transpose points (B,64,N) -> ptsT (B,N,64) ----------------
__global__ void transpose_kernel(const float* __restrict__ pts) {
    __shared__ float tile[32][33];
    int b = blockIdx.z;
    int n0 = blockIdx.x * 32;
    int d0 = blockIdx.y * 32;
    int tx = threadIdx.x, ty = threadIdx.y;
    tile[ty][tx] = pts[((size_t)b*Dx + d0 + ty)*Nx + n0 + tx];
    __syncthreads();
    g_ptsT[((size_t)b*Nx + n0 + ty)*Dx + d0 + tx] = tile[tx][ty];
}

// ---------------- FPS: one block per batch, 512 thr x 8 pts, ONE barrier/iter ----
__global__ __launch_bounds__(512) void fps_kernel(const float* __restrict__ xyz,
                                                  float* __restrict__ out) {
    int b = blockIdx.x;
    int t = threadIdx.x;
    int lane = t & 31, w = t >> 5;
    const float* xb = xyz + (size_t)b*3*Nx;

    float px[8], py[8], pz[8], dst[8];
#pragma unroll
    for (int i = 0; i < 8; i++) {
        int n = i*512 + t;
        px[i] = xb[n]; py[i] = xb[Nx+n]; pz[i] = xb[2*Nx+n];
        dst[i] = 1e10f;
    }

    __shared__ ull s_red[2][16];

    int far = 0;
    for (int s = 0; s < Sx; s++) {
        float cx = __ldg(xb + far);
        float cy = __ldg(xb + Nx + far);
        float cz = __ldg(xb + 2*Nx + far);
        if (t == 0) {
            out[b*3*Sx + s]        = cx;
            out[b*3*Sx + Sx + s]   = cy;
            out[b*3*Sx + 2*Sx + s] = cz;
            g_centers[(b*Sx + s)*3 + 0] = cx;
            g_centers[(b*Sx + s)*3 + 1] = cy;
            g_centers[(b*Sx + s)*3 + 2] = cz;
        }
        float best = -1.f; int bn = 0;
#pragma unroll
        for (int i = 0; i < 8; i++) {
            float dx = px[i]-cx, dy = py[i]-cy, dz = pz[i]-cz;
            float d = (dx*dx + dy*dy) + dz*dz;
            float nd = fminf(dst[i], d);
            dst[i] = nd;
            int n = i*512 + t;
            if (nd > best) { best = nd; bn = n; }  // ascending n: strict > keeps first max
        }
        // pack (dist, inverted index): max -> max dist, tie -> smallest index
        ull key = ((ull)__float_as_uint(best) << 32) | (unsigned)(0x7FFFFFFF - bn);
#pragma unroll
        for (int off = 16; off; off >>= 1) {
            ull o = __shfl_down_sync(0xffffffffu, key, off);
            if (o > key) key = o;
        }
        if (lane == 0) s_red[s & 1][w] = key;
        __syncthreads();
        ull k = (lane < 16) ? s_red[s & 1][lane] : 0ull;
#pragma unroll
        for (int off = 8; off; off >>= 1) {
            ull o = __shfl_down_sync(0xffffffffu, k, off);
            if (o > k) k = o;
        }
        k = __shfl_sync(0xffffffffu, k, 0);
        far = 0x7FFFFFFF - (int)(unsigned)(k & 0xFFFFFFFFull);
    }
}

// ---------------- ball query: one warp per centroid, 4 pts/thread ----------------
__global__ __launch_bounds__(256) void qb_kernel(const float* __restrict__ xyz) {
    int blk = blockIdx.x;          // B * S/8 = 2048
    int b = blk >> 7;
    int w = threadIdx.x >> 5;
    int s = (blk & 127)*8 + w;
    int lane = threadIdx.x & 31;

    __shared__ int buf[8][32];
    const float* xb = xyz + (size_t)b*3*Nx;

    float cx = g_centers[(b*Sx+s)*3 + 0];
    float cy = g_centers[(b*Sx+s)*3 + 1];
    float cz = g_centers[(b*Sx+s)*3 + 2];
    float s2 = (cx*cx + cy*cy) + cz*cz;

    int cnt = 0;
    for (int base = 0; base < Nx; base += 128) {
        int n0 = base + lane*4;
        float4 X4 = *reinterpret_cast<const float4*>(xb + n0);
        float4 Y4 = *reinterpret_cast<const float4*>(xb + Nx + n0);
        float4 Z4 = *reinterpret_cast<const float4*>(xb + 2*Nx + n0);
        unsigned msk = 0;
        {
            float dot = (cx*X4.x + cy*Y4.x) + cz*Z4.x;
            float d2  = (X4.x*X4.x + Y4.x*Y4.x) + Z4.x*Z4.x;
            float d = -2.f*dot; d += s2; d += d2;
            if (!(d > 0.01f)) msk |= 1u;
        }
        {
            float dot = (cx*X4.y + cy*Y4.y) + cz*Z4.y;
            float d2  = (X4.y*X4.y + Y4.y*Y4.y) + Z4.y*Z4.y;
            float d = -2.f*dot; d += s2; d += d2;
            if (!(d > 0.01f)) msk |= 2u;
        }
        {
            float dot = (cx*X4.z + cy*Y4.z) + cz*Z4.z;
            float d2  = (X4.z*X4.z + Y4.z*Y4.z) + Z4.z*Z4.z;
            float d = -2.f*dot; d += s2; d += d2;
            if (!(d > 0.01f)) msk |= 4u;
        }
        {
            float dot = (cx*X4.w + cy*Y4.w) + cz*Z4.w;
            float d2  = (X4.w*X4.w + Y4.w*Y4.w) + Z4.w*Z4.w;
            float d = -2.f*dot; d += s2; d += d2;
            if (!(d > 0.01f)) msk |= 8u;
        }
        int tc = __popc(msk);
        int inc = tc;
#pragma unroll
        for (int d = 1; d < 32; d <<= 1) {
            int v = __shfl_up_sync(0xffffffffu, inc, d);
            if (lane >= d) inc += v;
        }
        int excl = inc - tc;
        int total = __shfl_sync(0xffffffffu, inc, 31);
        int pos = cnt + excl;
#pragma unroll
        for (int j = 0; j < 4; j++) {
            if (msk & (1u << j)) { if (pos < Kx) buf[w][pos] = n0 + j; pos++; }
        }
        cnt += total;
        if (cnt >= Kx) break;
    }
    __syncwarp();
    int nv = cnt < Kx ? cnt : Kx;    // nv >= 1 always (centroid is its own neighbor)
    int first = buf[w][0];
    int v = (lane < nv) ? buf[w][lane] : first;
    g_gidx[(b*Sx + s)*Kx + lane] = v;
}

// ================= tiled MLP GEMM core =================
// Block: 64 outputs x 256 points. 256 threads, thread = (warp, og, pg):
//   lane = og*4 + pg;  outputs o = og*8..og*8+7;  points = warp*32 + pg*8 .. +7
// X tile staged in dyn smem as channel-pair (f32x2) rows; weights as pairs too.
// Epilogue writes Y and accumulates per-channel sum/sumsq stats.

template<int NC2>
__device__ __forceinline__ void mlp_core(
    const ull* __restrict__ s_x2, const ull* __restrict__ s_w2,
    const float* __restrict__ s_bias,
    float* __restrict__ s_sum, float* __restrict__ s_sq,
    float* __restrict__ Y, float* __restrict__ gsum, float* __restrict__ gsq,
    int o0, size_t p0)
{
    int tid = threadIdx.x;
    int warp = tid >> 5, lane = tid & 31;
    int og = lane >> 2, pg = lane & 3;
    int pl0 = warp*32 + pg*8;

    ull acc[64];
#pragma unroll
    for (int i = 0; i < 64; i++) acc[i] = 0ull;

#pragma unroll 2
    for (int c2 = 0; c2 < NC2; c2++) {
        ull wv[8], xv[8];
        const ulonglong2* wp = reinterpret_cast<const ulonglong2*>(s_w2 + (size_t)c2*64 + og*8);
        const ulonglong2* xp = reinterpret_cast<const ulonglong2*>(s_x2 + (size_t)c2*256 + pl0);
#pragma unroll
        for (int j = 0; j < 4; j++) {
            ulonglong2 a = wp[j]; wv[2*j] = a.x; wv[2*j+1] = a.y;
            ulonglong2 b = xp[j]; xv[2*j] = b.x; xv[2*j+1] = b.y;
        }
#pragma unroll
        for (int o = 0; o < 8; o++) {
#pragma unroll
            for (int p = 0; p < 8; p++) {
                ffma2(acc[o*8 + p], wv[o], xv[p]);
            }
        }
    }

    // epilogue: finish sums, write Y, accumulate stats
    float sacc[8], qacc[8];
#pragma unroll
    for (int o = 0; o < 8; o++) {
        int oo = og*8 + o;
        float bias = s_bias[oo];
        float y[8];
        float s = 0.f, q = 0.f;
#pragma unroll
        for (int p = 0; p < 8; p++) {
            float2 v = unpackf2(acc[o*8 + p]);
            y[p] = v.x + v.y + bias;
            s += y[p];
            q = fmaf(y[p], y[p], q);
        }
        float4 f0 = make_float4(y[0], y[1], y[2], y[3]);
        float4 f1 = make_float4(y[4], y[5], y[6], y[7]);
        float* dst = Y + (size_t)(o0 + oo)*Px + p0 + pl0;
        *reinterpret_cast<float4*>(dst)     = f0;
        *reinterpret_cast<float4*>(dst + 4) = f1;
        sacc[o] = s; qacc[o] = q;
    }
    // reduce over the 4 pg lanes in each quad
#pragma unroll
    for (int o = 0; o < 8; o++) {
        sacc[o] += __shfl_xor_sync(0xffffffffu, sacc[o], 1);
        sacc[o] += __shfl_xor_sync(0xffffffffu, sacc[o], 2);
        qacc[o] += __shfl_xor_sync(0xffffffffu, qacc[o], 1);
        qacc[o] += __shfl_xor_sync(0xffffffffu, qacc[o], 2);
    }
    if (pg == 0) {
#pragma unroll
        for (int o = 0; o < 8; o++) {
            atomicAdd(&s_sum[og*8 + o], sacc[o]);
            atomicAdd(&s_sq[og*8 + o],  qacc[o]);
        }
    }
    __syncthreads();
    if (tid < 64) {
        atomicAdd(gsum + o0 + tid, s_sum[tid]);
        atomicAdd(gsq  + o0 + tid, s_sq[tid]);
    }
}

// ---------------- layer 1: gather + GEMM (cin=68: 64 feat + 3 xyz + pad) -----
__global__ __launch_bounds__(256, 1) void mlp1_kernel(const float* __restrict__ xyz,
                                                      const float* __restrict__ W,
                                                      const float* __restrict__ bias,
                                                      float* __restrict__ Y,
                                                      float* __restrict__ gsum,
                                                      float* __restrict__ gsq) {
    constexpr int NC2 = 34;
    extern __shared__ ull sh[];
    ull* s_x2 = sh;                 // NC2*256
    ull* s_w2 = sh + NC2*256;       // NC2*64
    float* s_bias = reinterpret_cast<float*>(s_w2 + NC2*64);
    float* s_sum = s_bias + 64;
    float* s_sq  = s_sum + 64;

    int tid = threadIdx.x;
    size_t p0 = (size_t)blockIdx.x * 256;

    // stage weights (channel pairs)
    for (int i = tid; i < NC2*64; i += 256) {
        int c2 = i >> 6, o = i & 63;
        float lo, hi;
        if (c2 < 32)      { lo = W[o*67 + 3 + 2*c2]; hi = W[o*67 + 4 + 2*c2]; }
        else if (c2 == 32){ lo = W[o*67 + 0];        hi = W[o*67 + 1]; }
        else              { lo = W[o*67 + 2];        hi = 0.f; }
        s_w2[i] = packf2(lo, hi);
    }
    if (tid < 64) { s_bias[tid] = bias[tid]; s_sum[tid] = 0.f; s_sq[tid] = 0.f; }

    // stage X: gather point features + xyz-diff
    {
        size_t p = p0 + tid;
        int bs = (int)(p >> 5);
        int b = bs >> 10;
        int idx = g_gidx[p];
        const float4* row = reinterpret_cast<const float4*>(g_ptsT + ((size_t)b*Nx + idx)*Dx);
#pragma unroll
        for (int j = 0; j < 16; j++) {
            float4 v = row[j];
            s_x2[(size_t)(2*j)*256 + tid]   = packf2(v.x, v.y);
            s_x2[(size_t)(2*j+1)*256 + tid] = packf2(v.z, v.w);
        }
        float cx = g_centers[bs*3 + 0];
        float cy = g_centers[bs*3 + 1];
        float cz = g_centers[bs*3 + 2];
        const float* xb = xyz + (size_t)b*3*Nx;
        float dx = __ldg(xb + idx)        - cx;
        float dy = __ldg(xb + Nx + idx)   - cy;
        float dz = __ldg(xb + 2*Nx + idx) - cz;
        s_x2[(size_t)32*256 + tid] = packf2(dx, dy);
        s_x2[(size_t)33*256 + tid] = packf2(dz, 0.f);
    }
    __syncthreads();

    mlp_core<NC2>(s_x2, s_w2, s_bias, s_sum, s_sq, Y, gsum, gsq, 0, p0);
}

// ---------------- layers 2/3: BN+ReLU staged + GEMM ----------------
__global__ __launch_bounds__(256, 1) void mlp_bn_kernel(const float* __restrict__ X,
                                                        const float* __restrict__ W,
                                                        const float* __restrict__ bias,
                                                        const float* __restrict__ Aarr,
                                                        const float* __restrict__ Barr,
                                                        float* __restrict__ Y,
                                                        float* __restrict__ gsum,
                                                        float* __restrict__ gsq) {
    constexpr int NC2 = 32;
    extern __shared__ ull sh[];
    ull* s_x2 = sh;
    ull* s_w2 = sh + NC2*256;
    float* s_bias = reinterpret_cast<float*>(s_w2 + NC2*64);
    float* s_sum = s_bias + 64;
    float* s_sq  = s_sum + 64;

    int tid = threadIdx.x;
    int o0 = blockIdx.y * 64;
    size_t p0 = (size_t)blockIdx.x * 256;

    for (int i = tid; i < NC2*64; i += 256) {
        int c2 = i >> 6, o = i & 63;
        s_w2[i] = *reinterpret_cast<const ull*>(W + (size_t)(o0 + o)*64 + 2*c2);
    }
    if (tid < 64) { s_bias[tid] = bias[o0 + tid]; s_sum[tid] = 0.f; s_sq[tid] = 0.f; }

    // stage X with BN+ReLU applied once
#pragma unroll 4
    for (int c2 = 0; c2 < NC2; c2++) {
        int c = 2*c2;
        float xa = X[(size_t)c*Px + p0 + tid];
        float xb = X[(size_t)(c+1)*Px + p0 + tid];
        float va = fmaxf(fmaf(xa, Aarr[c],   Barr[c]),   0.f);
        float vb = fmaxf(fmaf(xb, Aarr[c+1], Barr[c+1]), 0.f);
        s_x2[(size_t)c2*256 + tid] = packf2(va, vb);
    }
    __syncthreads();

    mlp_core<NC2>(s_x2, s_w2, s_bias, s_sum, s_sq, Y, gsum, gsq, o0, p0);
}

// ---------------- BN finalize: A = gamma*rsqrt(var+eps), B = beta - mu*A ----
__global__ void finalize_kernel(int layer, const float* __restrict__ gamma,
                                const float* __restrict__ beta, int C) {
    int c = threadIdx.x;
    if (c >= C) return;
    float S = g_sum[layer*128 + c];
    float Q = g_sq[layer*128 + c];
    float m = S * (1.f/524288.f);          // 2^-19, exact
    float var = Q * (1.f/524288.f) - m*m;
    float A = gamma[c] * rsqrtf(var + 1e-5f);
    g_a[layer*128 + c]  = A;
    g_bb[layer*128 + c] = beta[c] - m*A;
}

// ---------------- final: BN+ReLU+max over group ----------------
__global__ __launch_bounds__(256) void max_kernel(const float* __restrict__ Y,
                                                  const float* __restrict__ A,
                                                  const float* __restrict__ B,
                                                  float* __restrict__ out) {
    int i = blockIdx.x*256 + threadIdx.x;   // over B*128*S = 2097152
    int b = i >> 17;
    int r = i & 131071;
    int c = r >> 10;
    int s = r & 1023;
    float a0 = A[c], b0 = B[c];
    const float4* yp = reinterpret_cast<const float4*>(Y + (size_t)c*Px + ((size_t)(b*Sx + s) << 5));
    float m = 0.f;   // ReLU floor
#pragma unroll
    for (int j = 0; j < 8; j++) {
        float4 y4 = yp[j];
        m = fmaxf(m, fmaf(y4.x, a0, b0));
        m = fmaxf(m, fmaf(y4.y, a0, b0));
        m = fmaxf(m, fmaf(y4.z, a0, b0));
        m = fmaxf(m, fmaf(y4.w, a0, b0));
    }
    out[16*3*1024 + i] = m;
}

// ---------------- launch ----------------
extern "C" void kernel_launch(void* const* d_in, const int* in_sizes, int n_in,
                              void* d_out, int out_size) {
    const float* xyz = (const float*)d_in[0];
    const float* pts = (const float*)d_in[1];
    const float* W0 = (const float*)d_in[2];
    const float* b0 = (const float*)d_in[3];
    const float* ga0 = (const float*)d_in[4];
    const float* be0 = (const float*)d_in[5];
    const float* W1 = (const float*)d_in[6];
    const float* b1 = (const float*)d_in[7];
    const float* ga1 = (const float*)d_in[8];
    const float* be1 = (const float*)d_in[9];
    const float* W2 = (const float*)d_in[10];
    const float* b2 = (const float*)d_in[11];
    const float* ga2 = (const float*)d_in[12];
    const float* be2 = (const float*)d_in[13];
    float* out = (float*)d_out;

    float *pY1, *pY2, *pY3, *pA, *pB, *pS, *pQ;
    cudaGetSymbolAddress((void**)&pY1, g_Y1);
    cudaGetSymbolAddress((void**)&pY2, g_Y2);
    cudaGetSymbolAddress((void**)&pY3, g_Y3);
    cudaGetSymbolAddress((void**)&pA, g_a);
    cudaGetSymbolAddress((void**)&pB, g_bb);
    cudaGetSymbolAddress((void**)&pS, g_sum);
    cudaGetSymbolAddress((void**)&pQ, g_sq);

    const int smem1 = (34*256 + 34*64)*8 + 192*4;
    const int smem2 = (32*256 + 32*64)*8 + 192*4;
    cudaFuncSetAttribute(mlp1_kernel, cudaFuncAttributeMaxDynamicSharedMemorySize, smem1);
    cudaFuncSetAttribute(mlp_bn_kernel, cudaFuncAttributeMaxDynamicSharedMemorySize, smem2);

    zero_stats_kernel<<<2, 256>>>();
    fps_kernel<<<Bx, 512>>>(xyz, out);
    qb_kernel<<<Bx*Sx/8, 256>>>(xyz);
    transpose_kernel<<<dim3(Nx/32, Dx/32, Bx), dim3(32, 32)>>>(pts);

    // layer 1: gather fused, 67(->68) -> 64
    mlp1_kernel<<<Px/256, 256, smem1>>>(xyz, W0, b0, pY1, pS + 0, pQ + 0);
    finalize_kernel<<<1, 128>>>(0, ga0, be0, 64);

    // layer 2: 64 -> 64, BN(layer0)+ReLU on input
    mlp_bn_kernel<<<dim3(Px/256, 1), 256, smem2>>>(pY1, W1, b1, pA + 0, pB + 0, pY2, pS + 128, pQ + 128);
    finalize_kernel<<<1, 128>>>(1, ga1, be1, 64);

    // layer 3: 64 -> 128, BN(layer1)+ReLU on input
    mlp_bn_kernel<<<dim3(Px/256, 2), 256, smem2>>>(pY2, W2, b2, pA + 128, pB + 128, pY3, pS + 256, pQ + 256);
    finalize_kernel<<<1, 128>>>(2, ga2, be2, 128);

    // BN(layer2)+ReLU + max over group -> output
    max_kernel<<<(Bx*128*Sx)/256, 256>>>(pY3, pA + 256, pB + 256, out);
}

// round 4
// speedup vs baseline: 1.1979x; 1.1979x over previous
#include <cuda_runtime.h>
#include <cuda_bf16.h>

#define Bx 16
#define Nx 4096
#define Sx 1024
#define Kx 32
#define Dx 64
#define Px (Bx*Sx*Kx)   // 524288

typedef unsigned long long ull;

// ---------------- device scratch (static, no allocation) ----------------
__device__ float g_centers[Bx*Sx*3];
__device__ int   g_gidx[Bx*Sx*Kx];
__device__ float g_ptsT[Bx*Nx*Dx];
__device__ float g_Y1[64u*Px];
__device__ float g_Y2[64u*Px];
__device__ float g_Y3[128u*Px];
__device__ float g_sum[384];
__device__ float g_sq[384];
__device__ float g_a[384];    // BN scale A = gamma*rsqrt(var+eps)
__device__ float g_bb[384];   // BN offset B = beta - mu*A

// ---------------- f32x2 helpers ----------------
__device__ __forceinline__ void ffma2(ull &acc, ull a, ull b) {
    asm("fma.rn.f32x2 %0, %1, %2, %0;" : "+l"(acc) : "l"(a), "l"(b));
}
__device__ __forceinline__ ull packf2(float lo, float hi) {
    ull r; asm("mov.b64 %0, {%1, %2};" : "=l"(r) : "f"(lo), "f"(hi)); return r;
}
__device__ __forceinline__ float2 unpackf2(ull v) {
    float lo, hi; asm("mov.b64 {%0, %1}, %2;" : "=f"(lo), "=f"(hi) : "l"(v));
    return make_float2(lo, hi);
}

// ---------------- zero stats ----------------
__global__ void zero_stats_kernel() {
    int t = blockIdx.x*256 + threadIdx.x;
    if (t < 384) { g_sum[t] = 0.f; g_sq[t] = 0.f; }
}

// ---------------- transpose points (B,64,N) -> ptsT (B,N,64) ----------------
__global__ void transpose_kernel(const float* __restrict__ pts) {
    __shared__ float tile[32][33];
    int b = blockIdx.z;
    int n0 = blockIdx.x * 32;
    int d0 = blockIdx.y * 32;
    int tx = threadIdx.x, ty = threadIdx.y;
    tile[ty][tx] = pts[((size_t)b*Dx + d0 + ty)*Nx + n0 + tx];
    __syncthreads();
    g_ptsT[((size_t)b*Nx + n0 + ty)*Dx + d0 + tx] = tile[tx][ty];
}

// ---------------- FPS: one block per batch (round-2 proven config) ----------
__global__ __launch_bounds__(256) void fps_kernel(const float* __restrict__ xyz,
                                                  float* __restrict__ out) {
    int b = blockIdx.x;
    int t = threadIdx.x;
    int lane = t & 31, w = t >> 5;
    const float* xb = xyz + (size_t)b*3*Nx;

    float px[16], py[16], pz[16], dst[16];
#pragma unroll
    for (int i = 0; i < 16; i++) {
        int n = i*256 + t;
        px[i] = xb[n]; py[i] = xb[Nx+n]; pz[i] = xb[2*Nx+n];
        dst[i] = 1e10f;
    }

    __shared__ ull s_red[2][8];

    int far = 0;
    for (int s = 0; s < Sx; s++) {
        float cx = __ldg(xb + far);
        float cy = __ldg(xb + Nx + far);
        float cz = __ldg(xb + 2*Nx + far);
        if (t == 0) {
            out[b*3*Sx + s]        = cx;
            out[b*3*Sx + Sx + s]   = cy;
            out[b*3*Sx + 2*Sx + s] = cz;
            g_centers[(b*Sx + s)*3 + 0] = cx;
            g_centers[(b*Sx + s)*3 + 1] = cy;
            g_centers[(b*Sx + s)*3 + 2] = cz;
        }
        float best = -1.f; int bn = 0;
#pragma unroll
        for (int i = 0; i < 16; i++) {
            float dx = px[i]-cx, dy = py[i]-cy, dz = pz[i]-cz;
            float d = (dx*dx + dy*dy) + dz*dz;
            float nd = fminf(dst[i], d);
            dst[i] = nd;
            int n = i*256 + t;
            if (nd > best) { best = nd; bn = n; }  // ascending n: strict > keeps first max
        }
        // pack (dist, inverted index): max -> max dist, tie -> smallest index
        ull key = ((ull)__float_as_uint(best) << 32) | (unsigned)(0x7FFFFFFF - bn);
#pragma unroll
        for (int off = 16; off; off >>= 1) {
            ull o = __shfl_down_sync(0xffffffffu, key, off);
            if (o > key) key = o;
        }
        if (lane == 0) s_red[s & 1][w] = key;
        __syncthreads();
        ull k = (lane < 8) ? s_red[s & 1][lane] : 0ull;
#pragma unroll
        for (int off = 4; off; off >>= 1) {
            ull o = __shfl_down_sync(0xffffffffu, k, off);
            if (o > k) k = o;
        }
        k = __shfl_sync(0xffffffffu, k, 0);
        far = 0x7FFFFFFF - (int)(unsigned)(k & 0xFFFFFFFFull);
    }
}

// ---------------- ball query: one warp per centroid, 4 pts/thread ----------------
__global__ __launch_bounds__(256) void qb_kernel(const float* __restrict__ xyz) {
    int blk = blockIdx.x;          // B * S/8 = 2048
    int b = blk >> 7;
    int w = threadIdx.x >> 5;
    int s = (blk & 127)*8 + w;
    int lane = threadIdx.x & 31;

    __shared__ int buf[8][32];
    const float* xb = xyz + (size_t)b*3*Nx;

    float cx = g_centers[(b*Sx+s)*3 + 0];
    float cy = g_centers[(b*Sx+s)*3 + 1];
    float cz = g_centers[(b*Sx+s)*3 + 2];
    float s2 = (cx*cx + cy*cy) + cz*cz;

    int cnt = 0;
    for (int base = 0; base < Nx; base += 128) {
        int n0 = base + lane*4;
        float4 X4 = *reinterpret_cast<const float4*>(xb + n0);
        float4 Y4 = *reinterpret_cast<const float4*>(xb + Nx + n0);
        float4 Z4 = *reinterpret_cast<const float4*>(xb + 2*Nx + n0);
        unsigned msk = 0;
        {
            float dot = (cx*X4.x + cy*Y4.x) + cz*Z4.x;
            float d2  = (X4.x*X4.x + Y4.x*Y4.x) + Z4.x*Z4.x;
            float d = -2.f*dot; d += s2; d += d2;
            if (!(d > 0.01f)) msk |= 1u;
        }
        {
            float dot = (cx*X4.y + cy*Y4.y) + cz*Z4.y;
            float d2  = (X4.y*X4.y + Y4.y*Y4.y) + Z4.y*Z4.y;
            float d = -2.f*dot; d += s2; d += d2;
            if (!(d > 0.01f)) msk |= 2u;
        }
        {
            float dot = (cx*X4.z + cy*Y4.z) + cz*Z4.z;
            float d2  = (X4.z*X4.z + Y4.z*Y4.z) + Z4.z*Z4.z;
            float d = -2.f*dot; d += s2; d += d2;
            if (!(d > 0.01f)) msk |= 4u;
        }
        {
            float dot = (cx*X4.w + cy*Y4.w) + cz*Z4.w;
            float d2  = (X4.w*X4.w + Y4.w*Y4.w) + Z4.w*Z4.w;
            float d = -2.f*dot; d += s2; d += d2;
            if (!(d > 0.01f)) msk |= 8u;
        }
        int tc = __popc(msk);
        int inc = tc;
#pragma unroll
        for (int d = 1; d < 32; d <<= 1) {
            int v = __shfl_up_sync(0xffffffffu, inc, d);
            if (lane >= d) inc += v;
        }
        int excl = inc - tc;
        int total = __shfl_sync(0xffffffffu, inc, 31);
        int pos = cnt + excl;
#pragma unroll
        for (int j = 0; j < 4; j++) {
            if (msk & (1u << j)) { if (pos < Kx) buf[w][pos] = n0 + j; pos++; }
        }
        cnt += total;
        if (cnt >= Kx) break;
    }
    __syncwarp();
    int nv = cnt < Kx ? cnt : Kx;    // nv >= 1 always (centroid is its own neighbor)
    int first = buf[w][0];
    int v = (lane < nv) ? buf[w][lane] : first;
    g_gidx[(b*Sx + s)*Kx + lane] = v;
}

// ================= tiled MLP GEMM core (point-pair f32x2) =================
// Block: 64 outputs x 256 points, 256 threads.
// Thread: og = lane&7 -> outputs og*8..og*8+7 ; ptg = tid>>3 -> points ptg*8..+7
// X tile in smem as point-pair ulls: s_x2[c*128 + p/2]  (lo = even point)
// W tile in smem duplicated pack(w,w), in-row slot permuted: slot(o) = (o&7)<<3 | (o>>3)
//   so thread og reads slots k*8+og  (contiguous 64B across og -> conflict-free LDS.64)

template<int NCH>
__device__ __forceinline__ void mlp_core(
    const ull* __restrict__ s_x2, const ull* __restrict__ s_w2,
    const float* __restrict__ s_bias,
    float* __restrict__ s_sum, float* __restrict__ s_sq,
    float* __restrict__ Y, float* __restrict__ gsum, float* __restrict__ gsq,
    int o0, size_t p0)
{
    int tid = threadIdx.x;
    int lane = tid & 31;
    int og = lane & 7;
    int ptg = tid >> 3;           // 0..31

    ull acc[8][4];
#pragma unroll
    for (int k = 0; k < 8; k++)
#pragma unroll
        for (int j = 0; j < 4; j++) acc[k][j] = 0ull;

#pragma unroll 2
    for (int c = 0; c < NCH; c++) {
        const ull* xrow = s_x2 + c*128 + ptg*4;
        ulonglong2 xa = *reinterpret_cast<const ulonglong2*>(xrow);
        ulonglong2 xb = *reinterpret_cast<const ulonglong2*>(xrow + 2);
        const ull* wrow = s_w2 + c*64 + og;
#pragma unroll
        for (int k = 0; k < 8; k++) {
            ull w = wrow[k*8];
            ffma2(acc[k][0], w, xa.x);
            ffma2(acc[k][1], w, xa.y);
            ffma2(acc[k][2], w, xb.x);
            ffma2(acc[k][3], w, xb.y);
        }
    }

    // epilogue: bias, write Y, fused stats
#pragma unroll
    for (int k = 0; k < 8; k++) {
        int oo = og*8 + k;
        float bias = s_bias[oo];
        float2 y0 = unpackf2(acc[k][0]);
        float2 y1 = unpackf2(acc[k][1]);
        float2 y2 = unpackf2(acc[k][2]);
        float2 y3 = unpackf2(acc[k][3]);
        float4 f0 = make_float4(y0.x + bias, y0.y + bias, y1.x + bias, y1.y + bias);
        float4 f1 = make_float4(y2.x + bias, y2.y + bias, y3.x + bias, y3.y + bias);
        float* dst = Y + (size_t)(o0 + oo)*Px + p0 + ptg*8;
        *reinterpret_cast<float4*>(dst)     = f0;
        *reinterpret_cast<float4*>(dst + 4) = f1;
        float s = ((f0.x + f0.y) + (f0.z + f0.w)) + ((f1.x + f1.y) + (f1.z + f1.w));
        float q = f0.x*f0.x + f0.y*f0.y + f0.z*f0.z + f0.w*f0.w
                + f1.x*f1.x + f1.y*f1.y + f1.z*f1.z + f1.w*f1.w;
        s += __shfl_xor_sync(0xffffffffu, s, 8);
        s += __shfl_xor_sync(0xffffffffu, s, 16);
        q += __shfl_xor_sync(0xffffffffu, q, 8);
        q += __shfl_xor_sync(0xffffffffu, q, 16);
        if (lane < 8) { atomicAdd(&s_sum[oo], s); atomicAdd(&s_sq[oo], q); }
    }
    __syncthreads();
    if (tid < 64) {
        atomicAdd(gsum + o0 + tid, s_sum[tid]);
        atomicAdd(gsq  + o0 + tid, s_sq[tid]);
    }
}

// ---------------- layer 1: gather + GEMM (cin=68: 64 feat + 3 xyz + pad) -----
__global__ __launch_bounds__(256, 2) void mlp1_kernel(const float* __restrict__ xyz,
                                                      const float* __restrict__ W,
                                                      const float* __restrict__ bias,
                                                      float* __restrict__ Y,
                                                      float* __restrict__ gsum,
                                                      float* __restrict__ gsq) {
    constexpr int NCH = 68;
    extern __shared__ ull sh[];
    ull* s_x2 = sh;                 // NCH*128
    ull* s_w2 = sh + NCH*128;       // NCH*64
    float* s_bias = reinterpret_cast<float*>(s_w2 + NCH*64);
    float* s_sum = s_bias + 64;
    float* s_sq  = s_sum + 64;

    int tid = threadIdx.x;
    size_t p0 = (size_t)blockIdx.x * 256;

    // stage weights: duplicated pack(w,w), permuted slot
    for (int i = tid; i < NCH*64; i += 256) {
        int c = i >> 6, o = i & 63;
        float wv;
        if (c < 64)      wv = W[o*67 + 3 + c];
        else if (c < 67) wv = W[o*67 + (c - 64)];
        else             wv = 0.f;
        int slot = ((o & 7) << 3) | (o >> 3);
        s_w2[c*64 + slot] = packf2(wv, wv);
    }
    if (tid < 64) { s_bias[tid] = bias[tid]; s_sum[tid] = 0.f; s_sq[tid] = 0.f; }

    // stage X: gather point features + xyz-diff (float view, column = tid)
    {
        float* s_xf = reinterpret_cast<float*>(s_x2);
        size_t p = p0 + tid;
        int bs = (int)(p >> 5);
        int b = bs >> 10;
        int idx = g_gidx[p];
        const float4* row = reinterpret_cast<const float4*>(g_ptsT + ((size_t)b*Nx + idx)*Dx);
#pragma unroll
        for (int j = 0; j < 16; j++) {
            float4 v = row[j];
            s_xf[(4*j + 0)*256 + tid] = v.x;
            s_xf[(4*j + 1)*256 + tid] = v.y;
            s_xf[(4*j + 2)*256 + tid] = v.z;
            s_xf[(4*j + 3)*256 + tid] = v.w;
        }
        float cx = g_centers[bs*3 + 0];
        float cy = g_centers[bs*3 + 1];
        float cz = g_centers[bs*3 + 2];
        const float* xb = xyz + (size_t)b*3*Nx;
        s_xf[64*256 + tid] = __ldg(xb + idx)        - cx;
        s_xf[65*256 + tid] = __ldg(xb + Nx + idx)   - cy;
        s_xf[66*256 + tid] = __ldg(xb + 2*Nx + idx) - cz;
        s_xf[67*256 + tid] = 0.f;
    }
    __syncthreads();

    mlp_core<NCH>(s_x2, s_w2, s_bias, s_sum, s_sq, Y, gsum, gsq, 0, p0);
}

// ---------------- layers 2/3: BN+ReLU staged + GEMM ----------------
__global__ __launch_bounds__(256, 2) void mlp_bn_kernel(const float* __restrict__ X,
                                                        const float* __restrict__ W,
                                                        const float* __restrict__ bias,
                                                        const float* __restrict__ Aarr,
                                                        const float* __restrict__ Barr,
                                                        float* __restrict__ Y,
                                                        float* __restrict__ gsum,
                                                        float* __restrict__ gsq) {
    constexpr int NCH = 64;
    extern __shared__ ull sh[];
    ull* s_x2 = sh;                 // 64*128
    ull* s_w2 = sh + NCH*128;       // 64*64
    float* s_bias = reinterpret_cast<float*>(s_w2 + NCH*64);
    float* s_sum = s_bias + 64;
    float* s_sq  = s_sum + 64;

    int tid = threadIdx.x;
    int o0 = blockIdx.y * 64;
    size_t p0 = (size_t)blockIdx.x * 256;

    // stage weights: duplicated pack(w,w), permuted slot
    for (int i = tid; i < NCH*64; i += 256) {
        int c = i >> 6, o = i & 63;
        float wv = W[(size_t)(o0 + o)*64 + c];
        int slot = ((o & 7) << 3) | (o >> 3);
        s_w2[c*64 + slot] = packf2(wv, wv);
    }
    if (tid < 64) { s_bias[tid] = bias[o0 + tid]; s_sum[tid] = 0.f; s_sq[tid] = 0.f; }

    // stage X with BN+ReLU applied once; coalesced LDG.128 + STS.128
#pragma unroll 4
    for (int i = tid; i < 64*64; i += 256) {
        int c = i >> 6, j = i & 63;
        float4 v = *reinterpret_cast<const float4*>(X + (size_t)c*Px + p0 + j*4);
        float A = Aarr[c], Bv = Barr[c];
        ulonglong2 w2;
        w2.x = packf2(fmaxf(fmaf(v.x, A, Bv), 0.f), fmaxf(fmaf(v.y, A, Bv), 0.f));
        w2.y = packf2(fmaxf(fmaf(v.z, A, Bv), 0.f), fmaxf(fmaf(v.w, A, Bv), 0.f));
        *reinterpret_cast<ulonglong2*>(s_x2 + c*128 + j*2) = w2;
    }
    __syncthreads();

    mlp_core<NCH>(s_x2, s_w2, s_bias, s_sum, s_sq, Y, gsum, gsq, o0, p0);
}

// ---------------- BN finalize: A = gamma*rsqrt(var+eps), B = beta - mu*A ----
__global__ void finalize_kernel(int layer, const float* __restrict__ gamma,
                                const float* __restrict__ beta, int C) {
    int c = threadIdx.x;
    if (c >= C) return;
    float S = g_sum[layer*128 + c];
    float Q = g_sq[layer*128 + c];
    float m = S * (1.f/524288.f);          // 2^-19, exact
    float var = Q * (1.f/524288.f) - m*m;
    float A = gamma[c] * rsqrtf(var + 1e-5f);
    g_a[layer*128 + c]  = A;
    g_bb[layer*128 + c] = beta[c] - m*A;
}

// ---------------- final: BN+ReLU+max over group ----------------
__global__ __launch_bounds__(256) void max_kernel(const float* __restrict__ Y,
                                                  const float* __restrict__ A,
                                                  const float* __restrict__ B,
                                                  float* __restrict__ out) {
    int i = blockIdx.x*256 + threadIdx.x;   // over B*128*S = 2097152
    int b = i >> 17;
    int r = i & 131071;
    int c = r >> 10;
    int s = r & 1023;
    float a0 = A[c], b0 = B[c];
    const float4* yp = reinterpret_cast<const float4*>(Y + (size_t)c*Px + ((size_t)(b*Sx + s) << 5));
    float m = 0.f;   // ReLU floor
#pragma unroll
    for (int j = 0; j < 8; j++) {
        float4 y4 = yp[j];
        m = fmaxf(m, fmaf(y4.x, a0, b0));
        m = fmaxf(m, fmaf(y4.y, a0, b0));
        m = fmaxf(m, fmaf(y4.z, a0, b0));
        m = fmaxf(m, fmaf(y4.w, a0, b0));
    }
    out[16*3*1024 + i] = m;
}

// ---------------- launch ----------------
extern "C" void kernel_launch(void* const* d_in, const int* in_sizes, int n_in,
                              void* d_out, int out_size) {
    const float* xyz = (const float*)d_in[0];
    const float* pts = (const float*)d_in[1];
    const float* W0 = (const float*)d_in[2];
    const float* b0 = (const float*)d_in[3];
    const float* ga0 = (const float*)d_in[4];
    const float* be0 = (const float*)d_in[5];
    const float* W1 = (const float*)d_in[6];
    const float* b1 = (const float*)d_in[7];
    const float* ga1 = (const float*)d_in[8];
    const float* be1 = (const float*)d_in[9];
    const float* W2 = (const float*)d_in[10];
    const float* b2 = (const float*)d_in[11];
    const float* ga2 = (const float*)d_in[12];
    const float* be2 = (const float*)d_in[13];
    float* out = (float*)d_out;

    float *pY1, *pY2, *pY3, *pA, *pB, *pS, *pQ;
    cudaGetSymbolAddress((void**)&pY1, g_Y1);
    cudaGetSymbolAddress((void**)&pY2, g_Y2);
    cudaGetSymbolAddress((void**)&pY3, g_Y3);
    cudaGetSymbolAddress((void**)&pA, g_a);
    cudaGetSymbolAddress((void**)&pB, g_bb);
    cudaGetSymbolAddress((void**)&pS, g_sum);
    cudaGetSymbolAddress((void**)&pQ, g_sq);

    const int smem1 = (68*128 + 68*64)*8 + 192*4;   // 105216 B
    const int smem2 = (64*128 + 64*64)*8 + 192*4;   // 99072 B
    cudaFuncSetAttribute(mlp1_kernel, cudaFuncAttributeMaxDynamicSharedMemorySize, smem1);
    cudaFuncSetAttribute(mlp_bn_kernel, cudaFuncAttributeMaxDynamicSharedMemorySize, smem2);

    zero_stats_kernel<<<2, 256>>>();
    fps_kernel<<<Bx, 256>>>(xyz, out);
    qb_kernel<<<Bx*Sx/8, 256>>>(xyz);
    transpose_kernel<<<dim3(Nx/32, Dx/32, Bx), dim3(32, 32)>>>(pts);

    // layer 1: gather fused, 67(->68) -> 64
    mlp1_kernel<<<Px/256, 256, smem1>>>(xyz, W0, b0, pY1, pS + 0, pQ + 0);
    finalize_kernel<<<1, 128>>>(0, ga0, be0, 64);

    // layer 2: 64 -> 64, BN(layer0)+ReLU on input
    mlp_bn_kernel<<<dim3(Px/256, 1), 256, smem2>>>(pY1, W1, b1, pA + 0, pB + 0, pY2, pS + 128, pQ + 128);
    finalize_kernel<<<1, 128>>>(1, ga1, be1, 64);

    // layer 3: 64 -> 128, BN(layer1)+ReLU on input
    mlp_bn_kernel<<<dim3(Px/256, 2), 256, smem2>>>(pY2, W2, b2, pA + 128, pB + 128, pY3, pS + 256, pQ + 256);
    finalize_kernel<<<1, 128>>>(2, ga2, be2, 128);

    // BN(layer2)+ReLU + max over group -> output
    max_kernel<<<(Bx*128*Sx)/256, 256>>>(pY3, pA + 256, pB + 256, out);
}

// round 5
// speedup vs baseline: 1.2662x; 1.0571x over previous
#include <cuda_runtime.h>
#include <cuda_bf16.h>

#define Bx 16
#define Nx 4096
#define Sx 1024
#define Kx 32
#define Dx 64
#define Px (Bx*Sx*Kx)   // 524288

typedef unsigned long long ull;

// ---------------- device scratch (static, no allocation) ----------------
__device__ float g_centers[Bx*Sx*3];
__device__ int   g_gidx[Bx*Sx*Kx];
__device__ float g_ptsT[Bx*Nx*Dx];
__device__ float g_Y1[64u*Px];
__device__ float g_Y2[64u*Px];
__device__ float g_Y3[128u*Px];
__device__ float g_sum[384];
__device__ float g_sq[384];
__device__ float g_a[384];    // BN scale A = gamma*rsqrt(var+eps)
__device__ float g_bb[384];   // BN offset B = beta - mu*A

// ---------------- f32x2 helpers ----------------
__device__ __forceinline__ void ffma2(ull &acc, ull a, ull b) {
    asm("fma.rn.f32x2 %0, %1, %2, %0;" : "+l"(acc) : "l"(a), "l"(b));
}
__device__ __forceinline__ ull packf2(float lo, float hi) {
    ull r; asm("mov.b64 %0, {%1, %2};" : "=l"(r) : "f"(lo), "f"(hi)); return r;
}
__device__ __forceinline__ float2 unpackf2(ull v) {
    float lo, hi; asm("mov.b64 {%0, %1}, %2;" : "=f"(lo), "=f"(hi) : "l"(v));
    return make_float2(lo, hi);
}

// ---------------- zero stats ----------------
__global__ void zero_stats_kernel() {
    int t = blockIdx.x*256 + threadIdx.x;
    if (t < 384) { g_sum[t] = 0.f; g_sq[t] = 0.f; }
}

// ---------------- transpose points (B,64,N) -> ptsT (B,N,64) ----------------
__global__ void transpose_kernel(const float* __restrict__ pts) {
    __shared__ float tile[32][33];
    int b = blockIdx.z;
    int n0 = blockIdx.x * 32;
    int d0 = blockIdx.y * 32;
    int tx = threadIdx.x, ty = threadIdx.y;
    tile[ty][tx] = pts[((size_t)b*Dx + d0 + ty)*Nx + n0 + tx];
    __syncthreads();
    g_ptsT[((size_t)b*Nx + n0 + ty)*Dx + d0 + tx] = tile[tx][ty];
}

// ---------------- FPS: one block per batch (round-2 proven config) ----------
__global__ __launch_bounds__(256) void fps_kernel(const float* __restrict__ xyz,
                                                  float* __restrict__ out) {
    int b = blockIdx.x;
    int t = threadIdx.x;
    int lane = t & 31, w = t >> 5;
    const float* xb = xyz + (size_t)b*3*Nx;

    float px[16], py[16], pz[16], dst[16];
#pragma unroll
    for (int i = 0; i < 16; i++) {
        int n = i*256 + t;
        px[i] = xb[n]; py[i] = xb[Nx+n]; pz[i] = xb[2*Nx+n];
        dst[i] = 1e10f;
    }

    __shared__ ull s_red[2][8];

    int far = 0;
    for (int s = 0; s < Sx; s++) {
        float cx = __ldg(xb + far);
        float cy = __ldg(xb + Nx + far);
        float cz = __ldg(xb + 2*Nx + far);
        if (t == 0) {
            out[b*3*Sx + s]        = cx;
            out[b*3*Sx + Sx + s]   = cy;
            out[b*3*Sx + 2*Sx + s] = cz;
            g_centers[(b*Sx + s)*3 + 0] = cx;
            g_centers[(b*Sx + s)*3 + 1] = cy;
            g_centers[(b*Sx + s)*3 + 2] = cz;
        }
        float best = -1.f; int bn = 0;
#pragma unroll
        for (int i = 0; i < 16; i++) {
            float dx = px[i]-cx, dy = py[i]-cy, dz = pz[i]-cz;
            float d = (dx*dx + dy*dy) + dz*dz;
            float nd = fminf(dst[i], d);
            dst[i] = nd;
            int n = i*256 + t;
            if (nd > best) { best = nd; bn = n; }  // ascending n: strict > keeps first max
        }
        // pack (dist, inverted index): max -> max dist, tie -> smallest index
        ull key = ((ull)__float_as_uint(best) << 32) | (unsigned)(0x7FFFFFFF - bn);
#pragma unroll
        for (int off = 16; off; off >>= 1) {
            ull o = __shfl_down_sync(0xffffffffu, key, off);
            if (o > key) key = o;
        }
        if (lane == 0) s_red[s & 1][w] = key;
        __syncthreads();
        ull k = (lane < 8) ? s_red[s & 1][lane] : 0ull;
#pragma unroll
        for (int off = 4; off; off >>= 1) {
            ull o = __shfl_down_sync(0xffffffffu, k, off);
            if (o > k) k = o;
        }
        k = __shfl_sync(0xffffffffu, k, 0);
        far = 0x7FFFFFFF - (int)(unsigned)(k & 0xFFFFFFFFull);
    }
}

// ---------------- ball query: one warp per centroid, 4 pts/thread ----------------
__global__ __launch_bounds__(256) void qb_kernel(const float* __restrict__ xyz) {
    int blk = blockIdx.x;          // B * S/8 = 2048
    int b = blk >> 7;
    int w = threadIdx.x >> 5;
    int s = (blk & 127)*8 + w;
    int lane = threadIdx.x & 31;

    __shared__ int buf[8][32];
    const float* xb = xyz + (size_t)b*3*Nx;

    float cx = g_centers[(b*Sx+s)*3 + 0];
    float cy = g_centers[(b*Sx+s)*3 + 1];
    float cz = g_centers[(b*Sx+s)*3 + 2];
    float s2 = (cx*cx + cy*cy) + cz*cz;

    int cnt = 0;
    for (int base = 0; base < Nx; base += 128) {
        int n0 = base + lane*4;
        float4 X4 = *reinterpret_cast<const float4*>(xb + n0);
        float4 Y4 = *reinterpret_cast<const float4*>(xb + Nx + n0);
        float4 Z4 = *reinterpret_cast<const float4*>(xb + 2*Nx + n0);
        unsigned msk = 0;
        {
            float dot = (cx*X4.x + cy*Y4.x) + cz*Z4.x;
            float d2  = (X4.x*X4.x + Y4.x*Y4.x) + Z4.x*Z4.x;
            float d = -2.f*dot; d += s2; d += d2;
            if (!(d > 0.01f)) msk |= 1u;
        }
        {
            float dot = (cx*X4.y + cy*Y4.y) + cz*Z4.y;
            float d2  = (X4.y*X4.y + Y4.y*Y4.y) + Z4.y*Z4.y;
            float d = -2.f*dot; d += s2; d += d2;
            if (!(d > 0.01f)) msk |= 2u;
        }
        {
            float dot = (cx*X4.z + cy*Y4.z) + cz*Z4.z;
            float d2  = (X4.z*X4.z + Y4.z*Y4.z) + Z4.z*Z4.z;
            float d = -2.f*dot; d += s2; d += d2;
            if (!(d > 0.01f)) msk |= 4u;
        }
        {
            float dot = (cx*X4.w + cy*Y4.w) + cz*Z4.w;
            float d2  = (X4.w*X4.w + Y4.w*Y4.w) + Z4.w*Z4.w;
            float d = -2.f*dot; d += s2; d += d2;
            if (!(d > 0.01f)) msk |= 8u;
        }
        int tc = __popc(msk);
        int inc = tc;
#pragma unroll
        for (int d = 1; d < 32; d <<= 1) {
            int v = __shfl_up_sync(0xffffffffu, inc, d);
            if (lane >= d) inc += v;
        }
        int excl = inc - tc;
        int total = __shfl_sync(0xffffffffu, inc, 31);
        int pos = cnt + excl;
#pragma unroll
        for (int j = 0; j < 4; j++) {
            if (msk & (1u << j)) { if (pos < Kx) buf[w][pos] = n0 + j; pos++; }
        }
        cnt += total;
        if (cnt >= Kx) break;
    }
    __syncwarp();
    int nv = cnt < Kx ? cnt : Kx;    // nv >= 1 always (centroid is its own neighbor)
    int first = buf[w][0];
    int v = (lane < nv) ? buf[w][lane] : first;
    g_gidx[(b*Sx + s)*Kx + lane] = v;
}

// ================= tiled MLP GEMM core (point-pair f32x2) =================
// Block: 64 outputs x 256 points, 256 threads.
// Thread: og = lane&7 -> outputs og*8..og*8+7 ; ptg = tid>>3 -> points ptg*8..+7
// X tile in smem as point-pair ulls: s_x2[c*128 + p/2]  (lo = even point)
// W tile in smem duplicated pack(w,w), in-row slot permuted: slot(o) = (o&7)<<3 | (o>>3)
//   so thread og reads slots k*8+og  (contiguous 64B across og -> conflict-free LDS.64)

template<int NCH>
__device__ __forceinline__ void mlp_core(
    const ull* __restrict__ s_x2, const ull* __restrict__ s_w2,
    const float* __restrict__ s_bias,
    float* __restrict__ s_sum, float* __restrict__ s_sq,
    float* __restrict__ Y, float* __restrict__ gsum, float* __restrict__ gsq,
    int o0, size_t p0)
{
    int tid = threadIdx.x;
    int lane = tid & 31;
    int og = lane & 7;
    int ptg = tid >> 3;           // 0..31

    ull acc[8][4];
#pragma unroll
    for (int k = 0; k < 8; k++)
#pragma unroll
        for (int j = 0; j < 4; j++) acc[k][j] = 0ull;

#pragma unroll 2
    for (int c = 0; c < NCH; c++) {
        const ull* xrow = s_x2 + c*128 + ptg*4;
        ulonglong2 xa = *reinterpret_cast<const ulonglong2*>(xrow);
        ulonglong2 xb = *reinterpret_cast<const ulonglong2*>(xrow + 2);
        const ull* wrow = s_w2 + c*64 + og;
#pragma unroll
        for (int k = 0; k < 8; k++) {
            ull w = wrow[k*8];
            ffma2(acc[k][0], w, xa.x);
            ffma2(acc[k][1], w, xa.y);
            ffma2(acc[k][2], w, xb.x);
            ffma2(acc[k][3], w, xb.y);
        }
    }

    // epilogue: bias, write Y, fused stats
#pragma unroll
    for (int k = 0; k < 8; k++) {
        int oo = og*8 + k;
        float bias = s_bias[oo];
        float2 y0 = unpackf2(acc[k][0]);
        float2 y1 = unpackf2(acc[k][1]);
        float2 y2 = unpackf2(acc[k][2]);
        float2 y3 = unpackf2(acc[k][3]);
        float4 f0 = make_float4(y0.x + bias, y0.y + bias, y1.x + bias, y1.y + bias);
        float4 f1 = make_float4(y2.x + bias, y2.y + bias, y3.x + bias, y3.y + bias);
        float* dst = Y + (size_t)(o0 + oo)*Px + p0 + ptg*8;
        *reinterpret_cast<float4*>(dst)     = f0;
        *reinterpret_cast<float4*>(dst + 4) = f1;
        float s = ((f0.x + f0.y) + (f0.z + f0.w)) + ((f1.x + f1.y) + (f1.z + f1.w));
        float q = f0.x*f0.x + f0.y*f0.y + f0.z*f0.z + f0.w*f0.w
                + f1.x*f1.x + f1.y*f1.y + f1.z*f1.z + f1.w*f1.w;
        s += __shfl_xor_sync(0xffffffffu, s, 8);
        s += __shfl_xor_sync(0xffffffffu, s, 16);
        q += __shfl_xor_sync(0xffffffffu, q, 8);
        q += __shfl_xor_sync(0xffffffffu, q, 16);
        if (lane < 8) { atomicAdd(&s_sum[oo], s); atomicAdd(&s_sq[oo], q); }
    }
    __syncthreads();
    if (tid < 64) {
        atomicAdd(gsum + o0 + tid, s_sum[tid]);
        atomicAdd(gsq  + o0 + tid, s_sq[tid]);
    }
}

// ---------------- layer 1: gather + GEMM (cin=68: 64 feat + 3 xyz + pad) -----
__global__ __launch_bounds__(256, 2) void mlp1_kernel(const float* __restrict__ xyz,
                                                      const float* __restrict__ W,
                                                      const float* __restrict__ bias,
                                                      float* __restrict__ Y,
                                                      float* __restrict__ gsum,
                                                      float* __restrict__ gsq) {
    constexpr int NCH = 68;
    extern __shared__ ull sh[];
    ull* s_x2 = sh;                 // NCH*128
    ull* s_w2 = sh + NCH*128;       // NCH*64
    float* s_bias = reinterpret_cast<float*>(s_w2 + NCH*64);
    float* s_sum = s_bias + 64;
    float* s_sq  = s_sum + 64;

    int tid = threadIdx.x;
    size_t p0 = (size_t)blockIdx.x * 256;

    // stage weights: duplicated pack(w,w), permuted slot
    for (int i = tid; i < NCH*64; i += 256) {
        int c = i >> 6, o = i & 63;
        float wv;
        if (c < 64)      wv = W[o*67 + 3 + c];
        else if (c < 67) wv = W[o*67 + (c - 64)];
        else             wv = 0.f;
        int slot = ((o & 7) << 3) | (o >> 3);
        s_w2[c*64 + slot] = packf2(wv, wv);
    }
    if (tid < 64) { s_bias[tid] = bias[tid]; s_sum[tid] = 0.f; s_sq[tid] = 0.f; }

    // stage X: gather point features + xyz-diff (float view, column = tid)
    {
        float* s_xf = reinterpret_cast<float*>(s_x2);
        size_t p = p0 + tid;
        int bs = (int)(p >> 5);
        int b = bs >> 10;
        int idx = g_gidx[p];
        const float4* row = reinterpret_cast<const float4*>(g_ptsT + ((size_t)b*Nx + idx)*Dx);
#pragma unroll
        for (int j = 0; j < 16; j++) {
            float4 v = row[j];
            s_xf[(4*j + 0)*256 + tid] = v.x;
            s_xf[(4*j + 1)*256 + tid] = v.y;
            s_xf[(4*j + 2)*256 + tid] = v.z;
            s_xf[(4*j + 3)*256 + tid] = v.w;
        }
        float cx = g_centers[bs*3 + 0];
        float cy = g_centers[bs*3 + 1];
        float cz = g_centers[bs*3 + 2];
        const float* xb = xyz + (size_t)b*3*Nx;
        s_xf[64*256 + tid] = __ldg(xb + idx)        - cx;
        s_xf[65*256 + tid] = __ldg(xb + Nx + idx)   - cy;
        s_xf[66*256 + tid] = __ldg(xb + 2*Nx + idx) - cz;
        s_xf[67*256 + tid] = 0.f;
    }
    __syncthreads();

    mlp_core<NCH>(s_x2, s_w2, s_bias, s_sum, s_sq, Y, gsum, gsq, 0, p0);
}

// ---------------- layers 2/3: BN+ReLU staged + GEMM ----------------
__global__ __launch_bounds__(256, 2) void mlp_bn_kernel(const float* __restrict__ X,
                                                        const float* __restrict__ W,
                                                        const float* __restrict__ bias,
                                                        const float* __restrict__ Aarr,
                                                        const float* __restrict__ Barr,
                                                        float* __restrict__ Y,
                                                        float* __restrict__ gsum,
                                                        float* __restrict__ gsq) {
    constexpr int NCH = 64;
    extern __shared__ ull sh[];
    ull* s_x2 = sh;                 // 64*128
    ull* s_w2 = sh + NCH*128;       // 64*64
    float* s_bias = reinterpret_cast<float*>(s_w2 + NCH*64);
    float* s_sum = s_bias + 64;
    float* s_sq  = s_sum + 64;

    int tid = threadIdx.x;
    int o0 = blockIdx.y * 64;
    size_t p0 = (size_t)blockIdx.x * 256;

    // stage weights: duplicated pack(w,w), permuted slot
    for (int i = tid; i < NCH*64; i += 256) {
        int c = i >> 6, o = i & 63;
        float wv = W[(size_t)(o0 + o)*64 + c];
        int slot = ((o & 7) << 3) | (o >> 3);
        s_w2[c*64 + slot] = packf2(wv, wv);
    }
    if (tid < 64) { s_bias[tid] = bias[o0 + tid]; s_sum[tid] = 0.f; s_sq[tid] = 0.f; }

    // stage X with BN+ReLU applied once; coalesced LDG.128 + STS.128
#pragma unroll 4
    for (int i = tid; i < 64*64; i += 256) {
        int c = i >> 6, j = i & 63;
        float4 v = *reinterpret_cast<const float4*>(X + (size_t)c*Px + p0 + j*4);
        float A = Aarr[c], Bv = Barr[c];
        ulonglong2 w2;
        w2.x = packf2(fmaxf(fmaf(v.x, A, Bv), 0.f), fmaxf(fmaf(v.y, A, Bv), 0.f));
        w2.y = packf2(fmaxf(fmaf(v.z, A, Bv), 0.f), fmaxf(fmaf(v.w, A, Bv), 0.f));
        *reinterpret_cast<ulonglong2*>(s_x2 + c*128 + j*2) = w2;
    }
    __syncthreads();

    mlp_core<NCH>(s_x2, s_w2, s_bias, s_sum, s_sq, Y, gsum, gsq, o0, p0);
}

// ---------------- BN finalize: A = gamma*rsqrt(var+eps), B = beta - mu*A ----
__global__ void finalize_kernel(int layer, const float* __restrict__ gamma,
                                const float* __restrict__ beta, int C) {
    int c = threadIdx.x;
    if (c >= C) return;
    float S = g_sum[layer*128 + c];
    float Q = g_sq[layer*128 + c];
    float m = S * (1.f/524288.f);          // 2^-19, exact
    float var = Q * (1.f/524288.f) - m*m;
    float A = gamma[c] * rsqrtf(var + 1e-5f);
    g_a[layer*128 + c]  = A;
    g_bb[layer*128 + c] = beta[c] - m*A;
}

// ---------------- final: BN+ReLU+max over group ----------------
__global__ __launch_bounds__(256) void max_kernel(const float* __restrict__ Y,
                                                  const float* __restrict__ A,
                                                  const float* __restrict__ B,
                                                  float* __restrict__ out) {
    int i = blockIdx.x*256 + threadIdx.x;   // over B*128*S = 2097152
    int b = i >> 17;
    int r = i & 131071;
    int c = r >> 10;
    int s = r & 1023;
    float a0 = A[c], b0 = B[c];
    const float4* yp = reinterpret_cast<const float4*>(Y + (size_t)c*Px + ((size_t)(b*Sx + s) << 5));
    float m = 0.f;   // ReLU floor
#pragma unroll
    for (int j = 0; j < 8; j++) {
        float4 y4 = yp[j];
        m = fmaxf(m, fmaf(y4.x, a0, b0));
        m = fmaxf(m, fmaf(y4.y, a0, b0));
        m = fmaxf(m, fmaf(y4.z, a0, b0));
        m = fmaxf(m, fmaf(y4.w, a0, b0));
    }
    out[16*3*1024 + i] = m;
}

// ---------------- launch ----------------
extern "C" void kernel_launch(void* const* d_in, const int* in_sizes, int n_in,
                              void* d_out, int out_size) {
    const float* xyz = (const float*)d_in[0];
    const float* pts = (const float*)d_in[1];
    const float* W0 = (const float*)d_in[2];
    const float* b0 = (const float*)d_in[3];
    const float* ga0 = (const float*)d_in[4];
    const float* be0 = (const float*)d_in[5];
    const float* W1 = (const float*)d_in[6];
    const float* b1 = (const float*)d_in[7];
    const float* ga1 = (const float*)d_in[8];
    const float* be1 = (const float*)d_in[9];
    const float* W2 = (const float*)d_in[10];
    const float* b2 = (const float*)d_in[11];
    const float* ga2 = (const float*)d_in[12];
    const float* be2 = (const float*)d_in[13];
    float* out = (float*)d_out;

    float *pY1, *pY2, *pY3, *pA, *pB, *pS, *pQ;
    cudaGetSymbolAddress((void**)&pY1, g_Y1);
    cudaGetSymbolAddress((void**)&pY2, g_Y2);
    cudaGetSymbolAddress((void**)&pY3, g_Y3);
    cudaGetSymbolAddress((void**)&pA, g_a);
    cudaGetSymbolAddress((void**)&pB, g_bb);
    cudaGetSymbolAddress((void**)&pS, g_sum);
    cudaGetSymbolAddress((void**)&pQ, g_sq);

    const int smem1 = (68*128 + 68*64)*8 + 192*4;   // 105216 B
    const int smem2 = (64*128 + 64*64)*8 + 192*4;   // 99072 B
    cudaFuncSetAttribute(mlp1_kernel, cudaFuncAttributeMaxDynamicSharedMemorySize, smem1);
    cudaFuncSetAttribute(mlp_bn_kernel, cudaFuncAttributeMaxDynamicSharedMemorySize, smem2);

    zero_stats_kernel<<<2, 256>>>();
    fps_kernel<<<Bx, 256>>>(xyz, out);
    qb_kernel<<<Bx*Sx/8, 256>>>(xyz);
    transpose_kernel<<<dim3(Nx/32, Dx/32, Bx), dim3(32, 32)>>>(pts);

    // layer 1: gather fused, 67(->68) -> 64
    mlp1_kernel<<<Px/256, 256, smem1>>>(xyz, W0, b0, pY1, pS + 0, pQ + 0);
    finalize_kernel<<<1, 128>>>(0, ga0, be0, 64);

    // layer 2: 64 -> 64, BN(layer0)+ReLU on input
    mlp_bn_kernel<<<dim3(Px/256, 1), 256, smem2>>>(pY1, W1, b1, pA + 0, pB + 0, pY2, pS + 128, pQ + 128);
    finalize_kernel<<<1, 128>>>(1, ga1, be1, 64);

    // layer 3: 64 -> 128, BN(layer1)+ReLU on input
    mlp_bn_kernel<<<dim3(Px/256, 2), 256, smem2>>>(pY2, W2, b2, pA + 128, pB + 128, pY3, pS + 256, pQ + 256);
    finalize_kernel<<<1, 128>>>(2, ga2, be2, 128);

    // BN(layer2)+ReLU + max over group -> output
    max_kernel<<<(Bx*128*Sx)/256, 256>>>(pY3, pA + 256, pB + 256, out);
}

// round 7
// speedup vs baseline: 1.4922x; 1.1785x over previous
#include <cuda_runtime.h>
#include <cuda_fp16.h>
#include <cstdint>

#define Bx 16
#define Nx 4096
#define Sx 1024
#define Kx 32
#define Dx 64
#define Px (Bx*Sx*Kx)   // 524288

typedef unsigned long long ull;

// ---------------- device scratch ----------------
__device__ float g_centers[Bx*Sx*3];
__device__ int   g_gidx[Bx*Sx*Kx];
__device__ float g_ptsT[Bx*Nx*Dx];
__device__ float g_Y1[64u*Px];
__device__ float g_Y2[64u*Px];
__device__ float g_Y3[128u*Px];
__device__ uint32_t g_W2h[64*32];    // packed half2 (hi), [o][c2]
__device__ uint32_t g_W2l[64*32];
__device__ uint32_t g_W3h[128*32];
__device__ uint32_t g_W3l[128*32];
__device__ float g_sum[384];
__device__ float g_sq[384];
__device__ float g_a[384];
__device__ float g_bb[384];

// ---------------- f32x2 helpers ----------------
__device__ __forceinline__ void ffma2(ull &acc, ull a, ull b) {
    asm("fma.rn.f32x2 %0, %1, %2, %0;" : "+l"(acc) : "l"(a), "l"(b));
}
__device__ __forceinline__ ull packf2(float lo, float hi) {
    ull r; asm("mov.b64 %0, {%1, %2};" : "=l"(r) : "f"(lo), "f"(hi)); return r;
}
__device__ __forceinline__ float2 unpackf2(ull v) {
    float lo, hi; asm("mov.b64 {%0, %1}, %2;" : "=f"(lo), "=f"(hi) : "l"(v));
    return make_float2(lo, hi);
}
__device__ __forceinline__ uint32_t packh2(float a, float b) {
    __half2 h = __halves2half2(__float2half_rn(a), __float2half_rn(b));
    return *reinterpret_cast<uint32_t*>(&h);
}
__device__ __forceinline__ void mma16816(float* d, const uint32_t* a, const uint32_t* b) {
    asm volatile(
        "mma.sync.aligned.m16n8k16.row.col.f32.f16.f16.f32 "
        "{%0,%1,%2,%3}, {%4,%5,%6,%7}, {%8,%9}, {%0,%1,%2,%3};"
        : "+f"(d[0]), "+f"(d[1]), "+f"(d[2]), "+f"(d[3])
        : "r"(a[0]), "r"(a[1]), "r"(a[2]), "r"(a[3]), "r"(b[0]), "r"(b[1]));
}

// ---------------- transpose points (B,64,N) -> ptsT (B,N,64) ----------------
__global__ void transpose_kernel(const float* __restrict__ pts) {
    __shared__ float tile[32][33];
    int b = blockIdx.z, n0 = blockIdx.x*32, d0 = blockIdx.y*32;
    int tx = threadIdx.x, ty = threadIdx.y;
    tile[ty][tx] = pts[((size_t)b*Dx + d0 + ty)*Nx + n0 + tx];
    __syncthreads();
    g_ptsT[((size_t)b*Nx + n0 + ty)*Dx + d0 + tx] = tile[tx][ty];
}

// ---------------- weight hi/lo split prep ----------------
__global__ void wprep_kernel(const float* __restrict__ W1, const float* __restrict__ W2) {
    int i = blockIdx.x*256 + threadIdx.x;   // over 128*32 = 4096
    if (i < 64*32) {
        int o = i >> 5, c2 = i & 31;
        float w0 = W1[o*64 + 2*c2], w1 = W1[o*64 + 2*c2 + 1];
        __half h0 = __float2half_rn(w0), h1 = __float2half_rn(w1);
        g_W2h[i] = packh2(w0, w1);
        g_W2l[i] = packh2(w0 - __half2float(h0), w1 - __half2float(h1));
    }
    if (i < 128*32) {
        int o = i >> 5, c2 = i & 31;
        float w0 = W2[o*64 + 2*c2], w1 = W2[o*64 + 2*c2 + 1];
        __half h0 = __float2half_rn(w0), h1 = __float2half_rn(w1);
        g_W3h[i] = packh2(w0, w1);
        g_W3l[i] = packh2(w0 - __half2float(h0), w1 - __half2float(h1));
    }
}

// ---------------- FPS (proven; stats-zero folded in) ----------------
__global__ __launch_bounds__(256) void fps_kernel(const float* __restrict__ xyz,
                                                  float* __restrict__ out) {
    int b = blockIdx.x, t = threadIdx.x;
    int lane = t & 31, w = t >> 5;
    if (b == 0) {
        if (t < 256) { g_sum[t] = 0.f; g_sq[t] = 0.f; }
        if (t < 128) { g_sum[256 + t] = 0.f; g_sq[256 + t] = 0.f; }
    }
    const float* xb = xyz + (size_t)b*3*Nx;
    float px[16], py[16], pz[16], dst[16];
#pragma unroll
    for (int i = 0; i < 16; i++) {
        int n = i*256 + t;
        px[i] = xb[n]; py[i] = xb[Nx+n]; pz[i] = xb[2*Nx+n];
        dst[i] = 1e10f;
    }
    __shared__ ull s_red[2][8];
    int far = 0;
    for (int s = 0; s < Sx; s++) {
        float cx = __ldg(xb + far), cy = __ldg(xb + Nx + far), cz = __ldg(xb + 2*Nx + far);
        if (t == 0) {
            out[b*3*Sx + s] = cx; out[b*3*Sx + Sx + s] = cy; out[b*3*Sx + 2*Sx + s] = cz;
            g_centers[(b*Sx+s)*3+0] = cx; g_centers[(b*Sx+s)*3+1] = cy; g_centers[(b*Sx+s)*3+2] = cz;
        }
        float best = -1.f; int bn = 0;
#pragma unroll
        for (int i = 0; i < 16; i++) {
            float dx = px[i]-cx, dy = py[i]-cy, dz = pz[i]-cz;
            float d = (dx*dx + dy*dy) + dz*dz;
            float nd = fminf(dst[i], d);
            dst[i] = nd;
            int n = i*256 + t;
            if (nd > best) { best = nd; bn = n; }
        }
        ull key = ((ull)__float_as_uint(best) << 32) | (unsigned)(0x7FFFFFFF - bn);
#pragma unroll
        for (int off = 16; off; off >>= 1) {
            ull o = __shfl_down_sync(0xffffffffu, key, off);
            if (o > key) key = o;
        }
        if (lane == 0) s_red[s & 1][w] = key;
        __syncthreads();
        ull k = (lane < 8) ? s_red[s & 1][lane] : 0ull;
#pragma unroll
        for (int off = 4; off; off >>= 1) {
            ull o = __shfl_down_sync(0xffffffffu, k, off);
            if (o > k) k = o;
        }
        k = __shfl_sync(0xffffffffu, k, 0);
        far = 0x7FFFFFFF - (int)(unsigned)(k & 0xFFFFFFFFull);
    }
}

// ---------------- ball query (proven) ----------------
__global__ __launch_bounds__(256) void qb_kernel(const float* __restrict__ xyz) {
    int blk = blockIdx.x;
    int b = blk >> 7;
    int w = threadIdx.x >> 5;
    int s = (blk & 127)*8 + w;
    int lane = threadIdx.x & 31;
    __shared__ int buf[8][32];
    const float* xb = xyz + (size_t)b*3*Nx;
    float cx = g_centers[(b*Sx+s)*3+0], cy = g_centers[(b*Sx+s)*3+1], cz = g_centers[(b*Sx+s)*3+2];
    float s2 = (cx*cx + cy*cy) + cz*cz;
    int cnt = 0;
    for (int base = 0; base < Nx; base += 128) {
        int n0 = base + lane*4;
        float4 X4 = *reinterpret_cast<const float4*>(xb + n0);
        float4 Y4 = *reinterpret_cast<const float4*>(xb + Nx + n0);
        float4 Z4 = *reinterpret_cast<const float4*>(xb + 2*Nx + n0);
        unsigned msk = 0;
        { float dot = (cx*X4.x + cy*Y4.x) + cz*Z4.x; float d2 = (X4.x*X4.x + Y4.x*Y4.x) + Z4.x*Z4.x;
          float d = -2.f*dot; d += s2; d += d2; if (!(d > 0.01f)) msk |= 1u; }
        { float dot = (cx*X4.y + cy*Y4.y) + cz*Z4.y; float d2 = (X4.y*X4.y + Y4.y*Y4.y) + Z4.y*Z4.y;
          float d = -2.f*dot; d += s2; d += d2; if (!(d > 0.01f)) msk |= 2u; }
        { float dot = (cx*X4.z + cy*Y4.z) + cz*Z4.z; float d2 = (X4.z*X4.z + Y4.z*Y4.z) + Z4.z*Z4.z;
          float d = -2.f*dot; d += s2; d += d2; if (!(d > 0.01f)) msk |= 4u; }
        { float dot = (cx*X4.w + cy*Y4.w) + cz*Z4.w; float d2 = (X4.w*X4.w + Y4.w*Y4.w) + Z4.w*Z4.w;
          float d = -2.f*dot; d += s2; d += d2; if (!(d > 0.01f)) msk |= 8u; }
        int tc = __popc(msk);
        int inc = tc;
#pragma unroll
        for (int d = 1; d < 32; d <<= 1) {
            int v = __shfl_up_sync(0xffffffffu, inc, d);
            if (lane >= d) inc += v;
        }
        int excl = inc - tc;
        int total = __shfl_sync(0xffffffffu, inc, 31);
        int pos = cnt + excl;
#pragma unroll
        for (int j = 0; j < 4; j++) {
            if (msk & (1u << j)) { if (pos < Kx) buf[w][pos] = n0 + j; pos++; }
        }
        cnt += total;
        if (cnt >= Kx) break;
    }
    __syncwarp();
    int nv = cnt < Kx ? cnt : Kx;
    int first = buf[w][0];
    int v = (lane < nv) ? buf[w][lane] : first;
    g_gidx[(b*Sx + s)*Kx + lane] = v;
}

// ================= R4 scalar MLP core (layer 1 only) =================
template<int NCH>
__device__ __forceinline__ void mlp_core(
    const ull* __restrict__ s_x2, const ull* __restrict__ s_w2,
    const float* __restrict__ s_bias,
    float* __restrict__ s_sum, float* __restrict__ s_sq,
    float* __restrict__ Y, float* __restrict__ gsum, float* __restrict__ gsq,
    int o0, size_t p0)
{
    int tid = threadIdx.x;
    int lane = tid & 31;
    int og = lane & 7;
    int ptg = tid >> 3;

    ull acc[8][4];
#pragma unroll
    for (int k = 0; k < 8; k++)
#pragma unroll
        for (int j = 0; j < 4; j++) acc[k][j] = 0ull;

#pragma unroll 2
    for (int c = 0; c < NCH; c++) {
        const ull* xrow = s_x2 + c*128 + ptg*4;
        ulonglong2 xa = *reinterpret_cast<const ulonglong2*>(xrow);
        ulonglong2 xb2 = *reinterpret_cast<const ulonglong2*>(xrow + 2);
        const ull* wrow = s_w2 + c*64 + og;
#pragma unroll
        for (int k = 0; k < 8; k++) {
            ull w = wrow[k*8];
            ffma2(acc[k][0], w, xa.x);
            ffma2(acc[k][1], w, xa.y);
            ffma2(acc[k][2], w, xb2.x);
            ffma2(acc[k][3], w, xb2.y);
        }
    }

#pragma unroll
    for (int k = 0; k < 8; k++) {
        int oo = og*8 + k;
        float bias = s_bias[oo];
        float2 y0 = unpackf2(acc[k][0]);
        float2 y1 = unpackf2(acc[k][1]);
        float2 y2 = unpackf2(acc[k][2]);
        float2 y3 = unpackf2(acc[k][3]);
        float4 f0 = make_float4(y0.x + bias, y0.y + bias, y1.x + bias, y1.y + bias);
        float4 f1 = make_float4(y2.x + bias, y2.y + bias, y3.x + bias, y3.y + bias);
        float* dst = Y + (size_t)(o0 + oo)*Px + p0 + ptg*8;
        *reinterpret_cast<float4*>(dst)     = f0;
        *reinterpret_cast<float4*>(dst + 4) = f1;
        float s = ((f0.x + f0.y) + (f0.z + f0.w)) + ((f1.x + f1.y) + (f1.z + f1.w));
        float q = f0.x*f0.x + f0.y*f0.y + f0.z*f0.z + f0.w*f0.w
                + f1.x*f1.x + f1.y*f1.y + f1.z*f1.z + f1.w*f1.w;
        s += __shfl_xor_sync(0xffffffffu, s, 8);
        s += __shfl_xor_sync(0xffffffffu, s, 16);
        q += __shfl_xor_sync(0xffffffffu, q, 8);
        q += __shfl_xor_sync(0xffffffffu, q, 16);
        if (lane < 8) { atomicAdd(&s_sum[oo], s); atomicAdd(&s_sq[oo], q); }
    }
    __syncthreads();
    if (tid < 64) {
        atomicAdd(gsum + o0 + tid, s_sum[tid]);
        atomicAdd(gsq  + o0 + tid, s_sq[tid]);
    }
}

// ---------------- layer 1: gather + scalar GEMM (R4 proven) ----------------
__global__ __launch_bounds__(256, 2) void mlp1_kernel(const float* __restrict__ xyz,
                                                      const float* __restrict__ W,
                                                      const float* __restrict__ bias,
                                                      float* __restrict__ Y,
                                                      float* __restrict__ gsum,
                                                      float* __restrict__ gsq) {
    constexpr int NCH = 68;
    extern __shared__ ull sh[];
    ull* s_x2 = sh;
    ull* s_w2 = sh + NCH*128;
    float* s_bias = reinterpret_cast<float*>(s_w2 + NCH*64);
    float* s_sum = s_bias + 64;
    float* s_sq  = s_sum + 64;

    int tid = threadIdx.x;
    size_t p0 = (size_t)blockIdx.x * 256;

    for (int i = tid; i < NCH*64; i += 256) {
        int c = i >> 6, o = i & 63;
        float wv;
        if (c < 64)      wv = W[o*67 + 3 + c];
        else if (c < 67) wv = W[o*67 + (c - 64)];
        else             wv = 0.f;
        int slot = ((o & 7) << 3) | (o >> 3);
        s_w2[c*64 + slot] = packf2(wv, wv);
    }
    if (tid < 64) { s_bias[tid] = bias[tid]; s_sum[tid] = 0.f; s_sq[tid] = 0.f; }
    {
        float* s_xf = reinterpret_cast<float*>(s_x2);
        size_t p = p0 + tid;
        int bs = (int)(p >> 5);
        int b = bs >> 10;
        int idx = g_gidx[p];
        const float4* row = reinterpret_cast<const float4*>(g_ptsT + ((size_t)b*Nx + idx)*Dx);
#pragma unroll
        for (int j = 0; j < 16; j++) {
            float4 v = row[j];
            s_xf[(4*j + 0)*256 + tid] = v.x;
            s_xf[(4*j + 1)*256 + tid] = v.y;
            s_xf[(4*j + 2)*256 + tid] = v.z;
            s_xf[(4*j + 3)*256 + tid] = v.w;
        }
        float cx = g_centers[bs*3+0], cy = g_centers[bs*3+1], cz = g_centers[bs*3+2];
        const float* xb = xyz + (size_t)b*3*Nx;
        s_xf[64*256 + tid] = __ldg(xb + idx)        - cx;
        s_xf[65*256 + tid] = __ldg(xb + Nx + idx)   - cy;
        s_xf[66*256 + tid] = __ldg(xb + 2*Nx + idx) - cz;
        s_xf[67*256 + tid] = 0.f;
    }
    __syncthreads();

    mlp_core<NCH>(s_x2, s_w2, s_bias, s_sum, s_sq, Y, gsum, gsq, 0, p0);
}

// ================= layers 2/3: mma.sync fp16-split GEMM =================
// A = W [NOUT x 64] (row-major), B = X [64 x 128pts] (col-major = pts rows in smem)
// 3 passes: Whi*Xhi + Whi*Xlo + Wlo*Xhi. D written channel-major + fused stats.
template<int NOUT>
__global__ __launch_bounds__(256) void mlp_mma_kernel(const float* __restrict__ X,
                                                      const uint32_t* __restrict__ Wh,
                                                      const uint32_t* __restrict__ Wl,
                                                      const float* __restrict__ bias,
                                                      const float* __restrict__ Aarr,
                                                      const float* __restrict__ Barr,
                                                      float* __restrict__ Y,
                                                      float* __restrict__ gsum,
                                                      float* __restrict__ gsq) {
    constexpr int PITCH = 36;                 // u32 per row (72 halves)
    constexpr int MW = (NOUT == 64) ? 2 : 4;  // warps along outputs
    constexpr int NW = 8 / MW;                // warps along points
    constexpr int NFR = (128 / NW) / 8;       // n-frags (8 pts) per warp
    extern __shared__ uint32_t sm[];
    uint32_t* s_xh = sm;                      // [128][PITCH]
    uint32_t* s_xl = sm + 128*PITCH;
    uint32_t* s_wh = sm + 256*PITCH;          // [NOUT][PITCH]
    uint32_t* s_wl = s_wh + NOUT*PITCH;
    float* s_bias = reinterpret_cast<float*>(s_wl + NOUT*PITCH);
    float* s_sum = s_bias + NOUT;
    float* s_sq  = s_sum + NOUT;

    int tid = threadIdx.x;
    int wid = tid >> 5, lane = tid & 31;
    int qr = lane >> 2, qc = lane & 3;
    size_t p0 = (size_t)blockIdx.x * 128;

    if (tid < NOUT) { s_bias[tid] = bias[tid]; s_sum[tid] = 0.f; s_sq[tid] = 0.f; }

    // stage weights
    for (int i = tid; i < NOUT*32; i += 256) {
        int o = i >> 5, c2 = i & 31;
        s_wh[o*PITCH + c2] = Wh[i];
        s_wl[o*PITCH + c2] = Wl[i];
    }
    // stage X: BN+ReLU + fp16 hi/lo split; [p][c] layout
    {
        int p = tid & 127;
        int ch0 = (tid >> 7) * 32;
#pragma unroll
        for (int j = 0; j < 16; j++) {
            int c = ch0 + 2*j;
            float v0 = X[(size_t)c*Px + p0 + p];
            float v1 = X[(size_t)(c+1)*Px + p0 + p];
            v0 = fmaxf(fmaf(v0, Aarr[c],   Barr[c]),   0.f);
            v1 = fmaxf(fmaf(v1, Aarr[c+1], Barr[c+1]), 0.f);
            __half h0 = __float2half_rn(v0), h1 = __float2half_rn(v1);
            __half2 hh = __halves2half2(h0, h1);
            s_xh[p*PITCH + (c >> 1)] = *reinterpret_cast<uint32_t*>(&hh);
            s_xl[p*PITCH + (c >> 1)] = packh2(v0 - __half2float(h0), v1 - __half2float(h1));
        }
    }
    __syncthreads();

    int mw = wid % MW, nw = wid / MW;
    int mbase = mw * 32;
    int pbase = nw * (128 / NW);

    float d[2][NFR][4];
#pragma unroll
    for (int mf = 0; mf < 2; mf++)
#pragma unroll
        for (int nf = 0; nf < NFR; nf++)
#pragma unroll
            for (int j = 0; j < 4; j++) d[mf][nf][j] = 0.f;

#pragma unroll
    for (int pass = 0; pass < 3; pass++) {
        const uint32_t* wsrc = (pass == 2) ? s_wl : s_wh;
        const uint32_t* xsrc = (pass == 1) ? s_xl : s_xh;
#pragma unroll
        for (int k0 = 0; k0 < 32; k0 += 8) {
            uint32_t a[2][4];
#pragma unroll
            for (int mf = 0; mf < 2; mf++) {
                int r0 = mbase + mf*16 + qr;
                a[mf][0] = wsrc[r0*PITCH + k0 + qc];
                a[mf][1] = wsrc[(r0+8)*PITCH + k0 + qc];
                a[mf][2] = wsrc[r0*PITCH + k0 + qc + 4];
                a[mf][3] = wsrc[(r0+8)*PITCH + k0 + qc + 4];
            }
            uint32_t b[NFR][2];
#pragma unroll
            for (int nf = 0; nf < NFR; nf++) {
                int p = pbase + nf*8 + qr;
                b[nf][0] = xsrc[p*PITCH + k0 + qc];
                b[nf][1] = xsrc[p*PITCH + k0 + qc + 4];
            }
#pragma unroll
            for (int mf = 0; mf < 2; mf++)
#pragma unroll
                for (int nf = 0; nf < NFR; nf++)
                    mma16816(d[mf][nf], a[mf], b[nf]);
        }
    }

    // epilogue: bias, channel-major store, fused stats
#pragma unroll
    for (int mf = 0; mf < 2; mf++) {
        int r0 = mbase + mf*16 + qr;
        float b0 = s_bias[r0], b8 = s_bias[r0 + 8];
        float s0 = 0.f, q0 = 0.f, s8 = 0.f, q8 = 0.f;
#pragma unroll
        for (int nf = 0; nf < NFR; nf++) {
            int p = pbase + nf*8 + 2*qc;
            float y0 = d[mf][nf][0] + b0, y1 = d[mf][nf][1] + b0;
            float y2 = d[mf][nf][2] + b8, y3 = d[mf][nf][3] + b8;
            *reinterpret_cast<float2*>(Y + (size_t)r0*Px + p0 + p)       = make_float2(y0, y1);
            *reinterpret_cast<float2*>(Y + (size_t)(r0+8)*Px + p0 + p)   = make_float2(y2, y3);
            s0 += y0 + y1; q0 += y0*y0 + y1*y1;
            s8 += y2 + y3; q8 += y2*y2 + y3*y3;
        }
        s0 += __shfl_xor_sync(0xffffffffu, s0, 1); s0 += __shfl_xor_sync(0xffffffffu, s0, 2);
        q0 += __shfl_xor_sync(0xffffffffu, q0, 1); q0 += __shfl_xor_sync(0xffffffffu, q0, 2);
        s8 += __shfl_xor_sync(0xffffffffu, s8, 1); s8 += __shfl_xor_sync(0xffffffffu, s8, 2);
        q8 += __shfl_xor_sync(0xffffffffu, q8, 1); q8 += __shfl_xor_sync(0xffffffffu, q8, 2);
        if (qc == 0) {
            atomicAdd(&s_sum[r0], s0);     atomicAdd(&s_sq[r0], q0);
            atomicAdd(&s_sum[r0 + 8], s8); atomicAdd(&s_sq[r0 + 8], q8);
        }
    }
    __syncthreads();
    if (tid < NOUT) {
        atomicAdd(gsum + tid, s_sum[tid]);
        atomicAdd(gsq  + tid, s_sq[tid]);
    }
}

// ---------------- BN finalize ----------------
__global__ void finalize_kernel(int layer, const float* __restrict__ gamma,
                                const float* __restrict__ beta, int C) {
    int c = threadIdx.x;
    if (c >= C) return;
    float S = g_sum[layer*128 + c], Q = g_sq[layer*128 + c];
    float m = S * (1.f/524288.f);
    float var = Q * (1.f/524288.f) - m*m;
    float A = gamma[c] * rsqrtf(var + 1e-5f);
    g_a[layer*128 + c]  = A;
    g_bb[layer*128 + c] = beta[c] - m*A;
}

// ---------------- final: BN+ReLU+max over group (channel-major) ----------------
__global__ __launch_bounds__(256) void max_kernel(const float* __restrict__ Y,
                                                  const float* __restrict__ A,
                                                  const float* __restrict__ B,
                                                  float* __restrict__ out) {
    int i = blockIdx.x*256 + threadIdx.x;
    int b = i >> 17;
    int r = i & 131071;
    int c = r >> 10;
    int s = r & 1023;
    float a0 = A[c], b0 = B[c];
    const float4* yp = reinterpret_cast<const float4*>(Y + (size_t)c*Px + ((size_t)(b*Sx + s) << 5));
    float m = 0.f;
#pragma unroll
    for (int j = 0; j < 8; j++) {
        float4 y4 = yp[j];
        m = fmaxf(m, fmaf(y4.x, a0, b0));
        m = fmaxf(m, fmaf(y4.y, a0, b0));
        m = fmaxf(m, fmaf(y4.z, a0, b0));
        m = fmaxf(m, fmaf(y4.w, a0, b0));
    }
    out[16*3*1024 + i] = m;
}

// ---------------- launch ----------------
extern "C" void kernel_launch(void* const* d_in, const int* in_sizes, int n_in,
                              void* d_out, int out_size) {
    const float* xyz = (const float*)d_in[0];
    const float* pts = (const float*)d_in[1];
    const float* W0 = (const float*)d_in[2];
    const float* b0 = (const float*)d_in[3];
    const float* ga0 = (const float*)d_in[4];
    const float* be0 = (const float*)d_in[5];
    const float* W1 = (const float*)d_in[6];
    const float* b1 = (const float*)d_in[7];
    const float* ga1 = (const float*)d_in[8];
    const float* be1 = (const float*)d_in[9];
    const float* W2 = (const float*)d_in[10];
    const float* b2 = (const float*)d_in[11];
    const float* ga2 = (const float*)d_in[12];
    const float* be2 = (const float*)d_in[13];
    float* out = (float*)d_out;

    float *pY1, *pY2, *pY3, *pA, *pB, *pS, *pQ;
    uint32_t *pW2h, *pW2l, *pW3h, *pW3l;
    cudaGetSymbolAddress((void**)&pY1, g_Y1);
    cudaGetSymbolAddress((void**)&pY2, g_Y2);
    cudaGetSymbolAddress((void**)&pY3, g_Y3);
    cudaGetSymbolAddress((void**)&pA, g_a);
    cudaGetSymbolAddress((void**)&pB, g_bb);
    cudaGetSymbolAddress((void**)&pS, g_sum);
    cudaGetSymbolAddress((void**)&pQ, g_sq);
    cudaGetSymbolAddress((void**)&pW2h, g_W2h);
    cudaGetSymbolAddress((void**)&pW2l, g_W2l);
    cudaGetSymbolAddress((void**)&pW3h, g_W3h);
    cudaGetSymbolAddress((void**)&pW3l, g_W3l);

    const int smem1 = (68*128 + 68*64)*8 + 192*4;
    const int smemM64  = (256*36 + 2*64*36)*4  + 64*3*4;    // 56064
    const int smemM128 = (256*36 + 2*128*36)*4 + 128*3*4;   // 75264
    cudaFuncSetAttribute(mlp1_kernel, cudaFuncAttributeMaxDynamicSharedMemorySize, smem1);
    cudaFuncSetAttribute(mlp_mma_kernel<64>,  cudaFuncAttributeMaxDynamicSharedMemorySize, smemM64);
    cudaFuncSetAttribute(mlp_mma_kernel<128>, cudaFuncAttributeMaxDynamicSharedMemorySize, smemM128);

    fps_kernel<<<Bx, 256>>>(xyz, out);                       // 1 (zeroes stats too)
    qb_kernel<<<Bx*Sx/8, 256>>>(xyz);                        // 2
    transpose_kernel<<<dim3(Nx/32, Dx/32, Bx), dim3(32, 32)>>>(pts); // 3
    mlp1_kernel<<<Px/256, 256, smem1>>>(xyz, W0, b0, pY1, pS + 0, pQ + 0);  // 4 (captured)
    wprep_kernel<<<16, 256>>>(W1, W2);                       // 5
    finalize_kernel<<<1, 128>>>(0, ga0, be0, 64);            // 6

    mlp_mma_kernel<64><<<Px/128, 256, smemM64>>>(
        pY1, pW2h, pW2l, b1, pA + 0, pB + 0, pY2, pS + 128, pQ + 128);
    finalize_kernel<<<1, 128>>>(1, ga1, be1, 64);

    mlp_mma_kernel<128><<<Px/128, 256, smemM128>>>(
        pY2, pW3h, pW3l, b2, pA + 128, pB + 128, pY3, pS + 256, pQ + 256);
    finalize_kernel<<<1, 128>>>(2, ga2, be2, 128);

    max_kernel<<<(Bx*128*Sx)/256, 256>>>(pY3, pA + 256, pB + 256, out);
}

// round 8
// speedup vs baseline: 1.9360x; 1.2974x over previous
#include <cuda_runtime.h>
#include <cuda_fp16.h>
#include <cstdint>

#define Bx 16
#define Nx 4096
#define Sx 1024
#define Kx 32
#define Dx 64
#define Px (Bx*Sx*Kx)   // 524288

typedef unsigned long long ull;

// ---------------- device scratch ----------------
__device__ float g_centers[Bx*Sx*3];
__device__ int   g_gidx[Bx*Sx*Kx];
__device__ float g_ptsT[Bx*Nx*Dx];
__device__ float g_Y1[64u*Px];          // channel-major
__device__ float g_Y2[64u*Px];          // channel-major
__device__ float g_gmax[Bx*Sx*128];     // [group][c] raw max of layer3 pre-BN
__device__ uint32_t g_W1h[64*40];       // layer1 packed half2, reordered channels
__device__ uint32_t g_W1l[64*40];
__device__ uint32_t g_W2h[64*32];
__device__ uint32_t g_W2l[64*32];
__device__ uint32_t g_W3h[128*32];
__device__ uint32_t g_W3l[128*32];
__device__ float g_sum[384];
__device__ float g_sq[384];
__device__ float g_a[384];
__device__ float g_bb[384];

__device__ __forceinline__ uint32_t packh2(float a, float b) {
    __half2 h = __halves2half2(__float2half_rn(a), __float2half_rn(b));
    return *reinterpret_cast<uint32_t*>(&h);
}
__device__ __forceinline__ void split2(float a, float b, uint32_t &hi, uint32_t &lo) {
    __half h0 = __float2half_rn(a), h1 = __float2half_rn(b);
    __half2 hh = __halves2half2(h0, h1);
    hi = *reinterpret_cast<uint32_t*>(&hh);
    lo = packh2(a - __half2float(h0), b - __half2float(h1));
}
__device__ __forceinline__ void mma16816(float* d, const uint32_t* a, const uint32_t* b) {
    asm volatile(
        "mma.sync.aligned.m16n8k16.row.col.f32.f16.f16.f32 "
        "{%0,%1,%2,%3}, {%4,%5,%6,%7}, {%8,%9}, {%0,%1,%2,%3};"
        : "+f"(d[0]), "+f"(d[1]), "+f"(d[2]), "+f"(d[3])
        : "r"(a[0]), "r"(a[1]), "r"(a[2]), "r"(a[3]), "r"(b[0]), "r"(b[1]));
}

// ---------------- transpose points (B,64,N) -> ptsT (B,N,64) ----------------
__global__ void transpose_kernel(const float* __restrict__ pts) {
    __shared__ float tile[32][33];
    int b = blockIdx.z, n0 = blockIdx.x*32, d0 = blockIdx.y*32;
    int tx = threadIdx.x, ty = threadIdx.y;
    tile[ty][tx] = pts[((size_t)b*Dx + d0 + ty)*Nx + n0 + tx];
    __syncthreads();
    g_ptsT[((size_t)b*Nx + n0 + ty)*Dx + d0 + tx] = tile[tx][ty];
}

// ---------------- weight split prep (all 3 layers) ----------------
__global__ void wprep_kernel(const float* __restrict__ W0,
                             const float* __restrict__ W1,
                             const float* __restrict__ W2) {
    int i = blockIdx.x*256 + threadIdx.x;   // up to 4096
    if (i < 64*40) {                         // layer1: reordered channels, K=80
        int o = i / 40, c2 = i % 40;
        float w[2];
#pragma unroll
        for (int j = 0; j < 2; j++) {
            int ch = 2*c2 + j;
            if (ch < 64)      w[j] = W0[o*67 + 3 + ch];
            else if (ch < 67) w[j] = W0[o*67 + (ch - 64)];
            else              w[j] = 0.f;
        }
        split2(w[0], w[1], g_W1h[i], g_W1l[i]);
    }
    if (i < 64*32) {
        int o = i >> 5, c2 = i & 31;
        split2(W1[o*64 + 2*c2], W1[o*64 + 2*c2 + 1], g_W2h[i], g_W2l[i]);
    }
    if (i < 128*32) {
        int o = i >> 5, c2 = i & 31;
        split2(W2[o*64 + 2*c2], W2[o*64 + 2*c2 + 1], g_W3h[i], g_W3l[i]);
    }
}

// ---------------- FPS: redux.sync argmax, one barrier/iter ----------------
__global__ __launch_bounds__(256) void fps_kernel(const float* __restrict__ xyz,
                                                  float* __restrict__ out) {
    int b = blockIdx.x, t = threadIdx.x;
    int lane = t & 31, w = t >> 5;
    if (b == 0) {
        if (t < 256) { g_sum[t] = 0.f; g_sq[t] = 0.f; }
        if (t < 128) { g_sum[256 + t] = 0.f; g_sq[256 + t] = 0.f; }
    }
    const float* xb = xyz + (size_t)b*3*Nx;
    float px[16], py[16], pz[16], dst[16];
#pragma unroll
    for (int i = 0; i < 16; i++) {
        int n = i*256 + t;
        px[i] = xb[n]; py[i] = xb[Nx+n]; pz[i] = xb[2*Nx+n];
        dst[i] = 1e10f;
    }
    __shared__ ull s_red[2][8];
    int far = 0;
    for (int s = 0; s < Sx; s++) {
        float cx = __ldg(xb + far), cy = __ldg(xb + Nx + far), cz = __ldg(xb + 2*Nx + far);
        if (t == 0) {
            out[b*3*Sx + s] = cx; out[b*3*Sx + Sx + s] = cy; out[b*3*Sx + 2*Sx + s] = cz;
            g_centers[(b*Sx+s)*3+0] = cx; g_centers[(b*Sx+s)*3+1] = cy; g_centers[(b*Sx+s)*3+2] = cz;
        }
        float best = -1.f; int bn = 0;
#pragma unroll
        for (int i = 0; i < 16; i++) {
            float dx = px[i]-cx, dy = py[i]-cy, dz = pz[i]-cz;
            float d = (dx*dx + dy*dy) + dz*dz;
            float nd = fminf(dst[i], d);
            dst[i] = nd;
            int n = i*256 + t;
            if (nd > best) { best = nd; bn = n; }   // first max kept (ascending n)
        }
        // warp argmax: dist>=0 so float bits are order-isomorphic
        unsigned ub = __float_as_uint(best);
        unsigned wmax = __reduce_max_sync(0xffffffffu, ub);
        unsigned cand = (ub == wmax) ? (unsigned)bn : 0xffffffffu;
        unsigned bmin = __reduce_min_sync(0xffffffffu, cand);
        if (lane == 0)
            s_red[s & 1][w] = ((ull)wmax << 32) | (unsigned)(0x7FFFFFFF - (int)bmin);
        __syncthreads();
        ull k = 0;
#pragma unroll
        for (int j = 0; j < 8; j++) { ull v = s_red[s & 1][j]; if (v > k) k = v; }
        far = 0x7FFFFFFF - (int)(unsigned)(k & 0xFFFFFFFFull);
    }
}

// ---------------- ball query (proven) ----------------
__global__ __launch_bounds__(256) void qb_kernel(const float* __restrict__ xyz) {
    int blk = blockIdx.x;
    int b = blk >> 7;
    int w = threadIdx.x >> 5;
    int s = (blk & 127)*8 + w;
    int lane = threadIdx.x & 31;
    __shared__ int buf[8][32];
    const float* xb = xyz + (size_t)b*3*Nx;
    float cx = g_centers[(b*Sx+s)*3+0], cy = g_centers[(b*Sx+s)*3+1], cz = g_centers[(b*Sx+s)*3+2];
    float s2 = (cx*cx + cy*cy) + cz*cz;
    int cnt = 0;
    for (int base = 0; base < Nx; base += 128) {
        int n0 = base + lane*4;
        float4 X4 = *reinterpret_cast<const float4*>(xb + n0);
        float4 Y4 = *reinterpret_cast<const float4*>(xb + Nx + n0);
        float4 Z4 = *reinterpret_cast<const float4*>(xb + 2*Nx + n0);
        unsigned msk = 0;
        { float dot = (cx*X4.x + cy*Y4.x) + cz*Z4.x; float d2 = (X4.x*X4.x + Y4.x*Y4.x) + Z4.x*Z4.x;
          float d = -2.f*dot; d += s2; d += d2; if (!(d > 0.01f)) msk |= 1u; }
        { float dot = (cx*X4.y + cy*Y4.y) + cz*Z4.y; float d2 = (X4.y*X4.y + Y4.y*Y4.y) + Z4.y*Z4.y;
          float d = -2.f*dot; d += s2; d += d2; if (!(d > 0.01f)) msk |= 2u; }
        { float dot = (cx*X4.z + cy*Y4.z) + cz*Z4.z; float d2 = (X4.z*X4.z + Y4.z*Y4.z) + Z4.z*Z4.z;
          float d = -2.f*dot; d += s2; d += d2; if (!(d > 0.01f)) msk |= 4u; }
        { float dot = (cx*X4.w + cy*Y4.w) + cz*Z4.w; float d2 = (X4.w*X4.w + Y4.w*Y4.w) + Z4.w*Z4.w;
          float d = -2.f*dot; d += s2; d += d2; if (!(d > 0.01f)) msk |= 8u; }
        int tc = __popc(msk);
        int inc = tc;
#pragma unroll
        for (int d = 1; d < 32; d <<= 1) {
            int v = __shfl_up_sync(0xffffffffu, inc, d);
            if (lane >= d) inc += v;
        }
        int excl = inc - tc;
        int total = __shfl_sync(0xffffffffu, inc, 31);
        int pos = cnt + excl;
#pragma unroll
        for (int j = 0; j < 4; j++) {
            if (msk & (1u << j)) { if (pos < Kx) buf[w][pos] = n0 + j; pos++; }
        }
        cnt += total;
        if (cnt >= Kx) break;
    }
    __syncwarp();
    int nv = cnt < Kx ? cnt : Kx;
    int first = buf[w][0];
    int v = (lane < nv) ? buf[w][lane] : first;
    g_gidx[(b*Sx + s)*Kx + lane] = v;
}

// ================= layer 1: gather + mma.sync fp16-split (K=80) =================
__global__ __launch_bounds__(256) void mlp1_mma_kernel(const float* __restrict__ xyz,
                                                       const float* __restrict__ bias,
                                                       float* __restrict__ Y,
                                                       float* __restrict__ gsum,
                                                       float* __restrict__ gsq) {
    constexpr int PITCH = 44;
    constexpr int NOUT = 64;
    constexpr int MW = 2, NW = 4, NFR = 4;
    extern __shared__ uint32_t sm[];
    uint32_t* s_xh = sm;                      // [128][PITCH]
    uint32_t* s_xl = sm + 128*PITCH;
    uint32_t* s_wh = sm + 256*PITCH;          // [64][PITCH]
    uint32_t* s_wl = s_wh + NOUT*PITCH;
    float* s_bias = reinterpret_cast<float*>(s_wl + NOUT*PITCH);
    float* s_sum = s_bias + NOUT;
    float* s_sq  = s_sum + NOUT;

    int tid = threadIdx.x;
    int wid = tid >> 5, lane = tid & 31;
    int qr = lane >> 2, qc = lane & 3;
    size_t p0 = (size_t)blockIdx.x * 128;

    if (tid < NOUT) { s_bias[tid] = bias[tid]; s_sum[tid] = 0.f; s_sq[tid] = 0.f; }
    for (int i = tid; i < NOUT*40; i += 256) {
        int o = i / 40, c2 = i % 40;
        s_wh[o*PITCH + c2] = g_W1h[i];
        s_wl[o*PITCH + c2] = g_W1l[i];
    }
    // stage X: gather + split. 2 threads/point.
    {
        int p = tid >> 1, h = tid & 1;
        size_t pp = p0 + p;
        int bs = (int)(pp >> 5);
        int b = bs >> 10;
        int idx = g_gidx[pp];
        const float4* row = reinterpret_cast<const float4*>(g_ptsT + ((size_t)b*Nx + idx)*Dx) + h*8;
#pragma unroll
        for (int j = 0; j < 8; j++) {
            float4 v = row[j];
            int c2 = h*16 + 2*j;
            split2(v.x, v.y, s_xh[p*PITCH + c2],     s_xl[p*PITCH + c2]);
            split2(v.z, v.w, s_xh[p*PITCH + c2 + 1], s_xl[p*PITCH + c2 + 1]);
        }
        if (h == 1) {
            float cx = g_centers[bs*3+0], cy = g_centers[bs*3+1], cz = g_centers[bs*3+2];
            const float* xb = xyz + (size_t)b*3*Nx;
            float dx = __ldg(xb + idx)        - cx;
            float dy = __ldg(xb + Nx + idx)   - cy;
            float dz = __ldg(xb + 2*Nx + idx) - cz;
            split2(dx, dy, s_xh[p*PITCH + 32], s_xl[p*PITCH + 32]);
            split2(dz, 0.f, s_xh[p*PITCH + 33], s_xl[p*PITCH + 33]);
#pragma unroll
            for (int c2 = 34; c2 < 40; c2++) { s_xh[p*PITCH + c2] = 0u; s_xl[p*PITCH + c2] = 0u; }
        }
    }
    __syncthreads();

    int mw = wid % MW, nw = wid / MW;
    int mbase = mw * 32;
    int pbase = nw * 32;

    float d[2][NFR][4];
#pragma unroll
    for (int mf = 0; mf < 2; mf++)
#pragma unroll
        for (int nf = 0; nf < NFR; nf++)
#pragma unroll
            for (int j = 0; j < 4; j++) d[mf][nf][j] = 0.f;

#pragma unroll
    for (int pass = 0; pass < 3; pass++) {
        const uint32_t* wsrc = (pass == 2) ? s_wl : s_wh;
        const uint32_t* xsrc = (pass == 1) ? s_xl : s_xh;
#pragma unroll
        for (int ks = 0; ks < 5; ks++) {
            int k0 = ks*8;
            uint32_t a[2][4];
#pragma unroll
            for (int mf = 0; mf < 2; mf++) {
                int r0 = mbase + mf*16 + qr;
                a[mf][0] = wsrc[r0*PITCH + k0 + qc];
                a[mf][1] = wsrc[(r0+8)*PITCH + k0 + qc];
                a[mf][2] = wsrc[r0*PITCH + k0 + qc + 4];
                a[mf][3] = wsrc[(r0+8)*PITCH + k0 + qc + 4];
            }
            uint32_t bb[NFR][2];
#pragma unroll
            for (int nf = 0; nf < NFR; nf++) {
                int p = pbase + nf*8 + qr;
                bb[nf][0] = xsrc[p*PITCH + k0 + qc];
                bb[nf][1] = xsrc[p*PITCH + k0 + qc + 4];
            }
#pragma unroll
            for (int mf = 0; mf < 2; mf++)
#pragma unroll
                for (int nf = 0; nf < NFR; nf++)
                    mma16816(d[mf][nf], a[mf], bb[nf]);
        }
    }

    // epilogue: channel-major Y + fused stats
#pragma unroll
    for (int mf = 0; mf < 2; mf++) {
        int r0 = mbase + mf*16 + qr;
        float b0 = s_bias[r0], b8 = s_bias[r0 + 8];
        float s0 = 0.f, q0 = 0.f, s8 = 0.f, q8 = 0.f;
#pragma unroll
        for (int nf = 0; nf < NFR; nf++) {
            int p = pbase + nf*8 + 2*qc;
            float y0 = d[mf][nf][0] + b0, y1 = d[mf][nf][1] + b0;
            float y2 = d[mf][nf][2] + b8, y3 = d[mf][nf][3] + b8;
            *reinterpret_cast<float2*>(Y + (size_t)r0*Px + p0 + p)     = make_float2(y0, y1);
            *reinterpret_cast<float2*>(Y + (size_t)(r0+8)*Px + p0 + p) = make_float2(y2, y3);
            s0 += y0 + y1; q0 += y0*y0 + y1*y1;
            s8 += y2 + y3; q8 += y2*y2 + y3*y3;
        }
        s0 += __shfl_xor_sync(0xffffffffu, s0, 1); s0 += __shfl_xor_sync(0xffffffffu, s0, 2);
        q0 += __shfl_xor_sync(0xffffffffu, q0, 1); q0 += __shfl_xor_sync(0xffffffffu, q0, 2);
        s8 += __shfl_xor_sync(0xffffffffu, s8, 1); s8 += __shfl_xor_sync(0xffffffffu, s8, 2);
        q8 += __shfl_xor_sync(0xffffffffu, q8, 1); q8 += __shfl_xor_sync(0xffffffffu, q8, 2);
        if (qc == 0) {
            atomicAdd(&s_sum[r0], s0);     atomicAdd(&s_sq[r0], q0);
            atomicAdd(&s_sum[r0 + 8], s8); atomicAdd(&s_sq[r0 + 8], q8);
        }
    }
    __syncthreads();
    if (tid < NOUT) {
        atomicAdd(gsum + tid, s_sum[tid]);
        atomicAdd(gsq  + tid, s_sq[tid]);
    }
}

// ================= layer 2: mma.sync fp16-split (R7 proven) =================
__global__ __launch_bounds__(256) void mlp2_mma_kernel(const float* __restrict__ X,
                                                       const uint32_t* __restrict__ Wh,
                                                       const uint32_t* __restrict__ Wl,
                                                       const float* __restrict__ bias,
                                                       const float* __restrict__ Aarr,
                                                       const float* __restrict__ Barr,
                                                       float* __restrict__ Y,
                                                       float* __restrict__ gsum,
                                                       float* __restrict__ gsq) {
    constexpr int PITCH = 36;
    constexpr int NOUT = 64;
    constexpr int MW = 2, NW = 4, NFR = 4;
    extern __shared__ uint32_t sm[];
    uint32_t* s_xh = sm;
    uint32_t* s_xl = sm + 128*PITCH;
    uint32_t* s_wh = sm + 256*PITCH;
    uint32_t* s_wl = s_wh + NOUT*PITCH;
    float* s_bias = reinterpret_cast<float*>(s_wl + NOUT*PITCH);
    float* s_sum = s_bias + NOUT;
    float* s_sq  = s_sum + NOUT;

    int tid = threadIdx.x;
    int wid = tid >> 5, lane = tid & 31;
    int qr = lane >> 2, qc = lane & 3;
    size_t p0 = (size_t)blockIdx.x * 128;

    if (tid < NOUT) { s_bias[tid] = bias[tid]; s_sum[tid] = 0.f; s_sq[tid] = 0.f; }
    for (int i = tid; i < NOUT*32; i += 256) {
        int o = i >> 5, c2 = i & 31;
        s_wh[o*PITCH + c2] = Wh[i];
        s_wl[o*PITCH + c2] = Wl[i];
    }
    {
        int p = tid & 127;
        int ch0 = (tid >> 7) * 32;
#pragma unroll
        for (int j = 0; j < 16; j++) {
            int c = ch0 + 2*j;
            float v0 = X[(size_t)c*Px + p0 + p];
            float v1 = X[(size_t)(c+1)*Px + p0 + p];
            v0 = fmaxf(fmaf(v0, Aarr[c],   Barr[c]),   0.f);
            v1 = fmaxf(fmaf(v1, Aarr[c+1], Barr[c+1]), 0.f);
            split2(v0, v1, s_xh[p*PITCH + (c >> 1)], s_xl[p*PITCH + (c >> 1)]);
        }
    }
    __syncthreads();

    int mw = wid % MW, nw = wid / MW;
    int mbase = mw * 32;
    int pbase = nw * 32;

    float d[2][NFR][4];
#pragma unroll
    for (int mf = 0; mf < 2; mf++)
#pragma unroll
        for (int nf = 0; nf < NFR; nf++)
#pragma unroll
            for (int j = 0; j < 4; j++) d[mf][nf][j] = 0.f;

#pragma unroll
    for (int pass = 0; pass < 3; pass++) {
        const uint32_t* wsrc = (pass == 2) ? s_wl : s_wh;
        const uint32_t* xsrc = (pass == 1) ? s_xl : s_xh;
#pragma unroll
        for (int k0 = 0; k0 < 32; k0 += 8) {
            uint32_t a[2][4];
#pragma unroll
            for (int mf = 0; mf < 2; mf++) {
                int r0 = mbase + mf*16 + qr;
                a[mf][0] = wsrc[r0*PITCH + k0 + qc];
                a[mf][1] = wsrc[(r0+8)*PITCH + k0 + qc];
                a[mf][2] = wsrc[r0*PITCH + k0 + qc + 4];
                a[mf][3] = wsrc[(r0+8)*PITCH + k0 + qc + 4];
            }
            uint32_t bb[NFR][2];
#pragma unroll
            for (int nf = 0; nf < NFR; nf++) {
                int p = pbase + nf*8 + qr;
                bb[nf][0] = xsrc[p*PITCH + k0 + qc];
                bb[nf][1] = xsrc[p*PITCH + k0 + qc + 4];
            }
#pragma unroll
            for (int mf = 0; mf < 2; mf++)
#pragma unroll
                for (int nf = 0; nf < NFR; nf++)
                    mma16816(d[mf][nf], a[mf], bb[nf]);
        }
    }

#pragma unroll
    for (int mf = 0; mf < 2; mf++) {
        int r0 = mbase + mf*16 + qr;
        float b0 = s_bias[r0], b8 = s_bias[r0 + 8];
        float s0 = 0.f, q0 = 0.f, s8 = 0.f, q8 = 0.f;
#pragma unroll
        for (int nf = 0; nf < NFR; nf++) {
            int p = pbase + nf*8 + 2*qc;
            float y0 = d[mf][nf][0] + b0, y1 = d[mf][nf][1] + b0;
            float y2 = d[mf][nf][2] + b8, y3 = d[mf][nf][3] + b8;
            *reinterpret_cast<float2*>(Y + (size_t)r0*Px + p0 + p)     = make_float2(y0, y1);
            *reinterpret_cast<float2*>(Y + (size_t)(r0+8)*Px + p0 + p) = make_float2(y2, y3);
            s0 += y0 + y1; q0 += y0*y0 + y1*y1;
            s8 += y2 + y3; q8 += y2*y2 + y3*y3;
        }
        s0 += __shfl_xor_sync(0xffffffffu, s0, 1); s0 += __shfl_xor_sync(0xffffffffu, s0, 2);
        q0 += __shfl_xor_sync(0xffffffffu, q0, 1); q0 += __shfl_xor_sync(0xffffffffu, q0, 2);
        s8 += __shfl_xor_sync(0xffffffffu, s8, 1); s8 += __shfl_xor_sync(0xffffffffu, s8, 2);
        q8 += __shfl_xor_sync(0xffffffffu, q8, 1); q8 += __shfl_xor_sync(0xffffffffu, q8, 2);
        if (qc == 0) {
            atomicAdd(&s_sum[r0], s0);     atomicAdd(&s_sq[r0], q0);
            atomicAdd(&s_sum[r0 + 8], s8); atomicAdd(&s_sq[r0 + 8], q8);
        }
    }
    __syncthreads();
    if (tid < NOUT) {
        atomicAdd(gsum + tid, s_sum[tid]);
        atomicAdd(gsq  + tid, s_sq[tid]);
    }
}

// ================= layer 3: mma.sync, epilogue = stats + group-max (no Y store) ====
__global__ __launch_bounds__(256) void mlp3_mma_kernel(const float* __restrict__ X,
                                                       const uint32_t* __restrict__ Wh,
                                                       const uint32_t* __restrict__ Wl,
                                                       const float* __restrict__ bias,
                                                       const float* __restrict__ Aarr,
                                                       const float* __restrict__ Barr,
                                                       float* __restrict__ gmax,
                                                       float* __restrict__ gsum,
                                                       float* __restrict__ gsq) {
    constexpr int PITCH = 36;
    constexpr int NOUT = 128;
    constexpr int MW = 4, NW = 2, NFR = 8;
    extern __shared__ uint32_t sm[];
    uint32_t* s_xh = sm;
    uint32_t* s_xl = sm + 128*PITCH;
    uint32_t* s_wh = sm + 256*PITCH;
    uint32_t* s_wl = s_wh + NOUT*PITCH;
    float* s_bias = reinterpret_cast<float*>(s_wl + NOUT*PITCH);
    float* s_sum = s_bias + NOUT;
    float* s_sq  = s_sum + NOUT;

    int tid = threadIdx.x;
    int wid = tid >> 5, lane = tid & 31;
    int qr = lane >> 2, qc = lane & 3;
    size_t p0 = (size_t)blockIdx.x * 128;

    if (tid < NOUT) { s_bias[tid] = bias[tid]; s_sum[tid] = 0.f; s_sq[tid] = 0.f; }
    for (int i = tid; i < NOUT*32; i += 256) {
        int o = i >> 5, c2 = i & 31;
        s_wh[o*PITCH + c2] = Wh[i];
        s_wl[o*PITCH + c2] = Wl[i];
    }
    {
        int p = tid & 127;
        int ch0 = (tid >> 7) * 32;
#pragma unroll
        for (int j = 0; j < 16; j++) {
            int c = ch0 + 2*j;
            float v0 = X[(size_t)c*Px + p0 + p];
            float v1 = X[(size_t)(c+1)*Px + p0 + p];
            v0 = fmaxf(fmaf(v0, Aarr[c],   Barr[c]),   0.f);
            v1 = fmaxf(fmaf(v1, Aarr[c+1], Barr[c+1]), 0.f);
            split2(v0, v1, s_xh[p*PITCH + (c >> 1)], s_xl[p*PITCH + (c >> 1)]);
        }
    }
    __syncthreads();

    int mw = wid % MW, nw = wid / MW;
    int mbase = mw * 32;
    int pbase = nw * 64;

    float d[2][NFR][4];
#pragma unroll
    for (int mf = 0; mf < 2; mf++)
#pragma unroll
        for (int nf = 0; nf < NFR; nf++)
#pragma unroll
            for (int j = 0; j < 4; j++) d[mf][nf][j] = 0.f;

#pragma unroll
    for (int pass = 0; pass < 3; pass++) {
        const uint32_t* wsrc = (pass == 2) ? s_wl : s_wh;
        const uint32_t* xsrc = (pass == 1) ? s_xl : s_xh;
#pragma unroll
        for (int k0 = 0; k0 < 32; k0 += 8) {
            uint32_t a[2][4];
#pragma unroll
            for (int mf = 0; mf < 2; mf++) {
                int r0 = mbase + mf*16 + qr;
                a[mf][0] = wsrc[r0*PITCH + k0 + qc];
                a[mf][1] = wsrc[(r0+8)*PITCH + k0 + qc];
                a[mf][2] = wsrc[r0*PITCH + k0 + qc + 4];
                a[mf][3] = wsrc[(r0+8)*PITCH + k0 + qc + 4];
            }
            uint32_t bb[NFR][2];
#pragma unroll
            for (int nf = 0; nf < NFR; nf++) {
                int p = pbase + nf*8 + qr;
                bb[nf][0] = xsrc[p*PITCH + k0 + qc];
                bb[nf][1] = xsrc[p*PITCH + k0 + qc + 4];
            }
#pragma unroll
            for (int mf = 0; mf < 2; mf++)
#pragma unroll
                for (int nf = 0; nf < NFR; nf++)
                    mma16816(d[mf][nf], a[mf], bb[nf]);
        }
    }

    // epilogue: stats + per-group raw max (groups of 32 pts; tile = 4 groups)
#pragma unroll
    for (int mf = 0; mf < 2; mf++) {
        int r0 = mbase + mf*16 + qr;
        float b0 = s_bias[r0], b8 = s_bias[r0 + 8];
        float s0 = 0.f, q0 = 0.f, s8 = 0.f, q8 = 0.f;
        float m0[2] = {-3.4e38f, -3.4e38f};
        float m8[2] = {-3.4e38f, -3.4e38f};
#pragma unroll
        for (int nf = 0; nf < NFR; nf++) {
            int g = nf >> 2;
            float y0 = d[mf][nf][0] + b0, y1 = d[mf][nf][1] + b0;
            float y2 = d[mf][nf][2] + b8, y3 = d[mf][nf][3] + b8;
            s0 += y0 + y1; q0 += y0*y0 + y1*y1;
            s8 += y2 + y3; q8 += y2*y2 + y3*y3;
            m0[g] = fmaxf(m0[g], fmaxf(y0, y1));
            m8[g] = fmaxf(m8[g], fmaxf(y2, y3));
        }
        s0 += __shfl_xor_sync(0xffffffffu, s0, 1); s0 += __shfl_xor_sync(0xffffffffu, s0, 2);
        q0 += __shfl_xor_sync(0xffffffffu, q0, 1); q0 += __shfl_xor_sync(0xffffffffu, q0, 2);
        s8 += __shfl_xor_sync(0xffffffffu, s8, 1); s8 += __shfl_xor_sync(0xffffffffu, s8, 2);
        q8 += __shfl_xor_sync(0xffffffffu, q8, 1); q8 += __shfl_xor_sync(0xffffffffu, q8, 2);
#pragma unroll
        for (int g = 0; g < 2; g++) {
            m0[g] = fmaxf(m0[g], __shfl_xor_sync(0xffffffffu, m0[g], 1));
            m0[g] = fmaxf(m0[g], __shfl_xor_sync(0xffffffffu, m0[g], 2));
            m8[g] = fmaxf(m8[g], __shfl_xor_sync(0xffffffffu, m8[g], 1));
            m8[g] = fmaxf(m8[g], __shfl_xor_sync(0xffffffffu, m8[g], 2));
        }
        if (qc == 0) {
            atomicAdd(&s_sum[r0], s0);     atomicAdd(&s_sq[r0], q0);
            atomicAdd(&s_sum[r0 + 8], s8); atomicAdd(&s_sq[r0 + 8], q8);
            int gbase = blockIdx.x*4 + nw*2;
#pragma unroll
            for (int g = 0; g < 2; g++) {
                gmax[(size_t)(gbase + g)*128 + r0]     = m0[g];
                gmax[(size_t)(gbase + g)*128 + r0 + 8] = m8[g];
            }
        }
    }
    __syncthreads();
    if (tid < NOUT) {
        atomicAdd(gsum + tid, s_sum[tid]);
        atomicAdd(gsq  + tid, s_sq[tid]);
    }
}

// ---------------- BN finalize ----------------
__global__ void finalize_kernel(int layer, const float* __restrict__ gamma,
                                const float* __restrict__ beta, int C) {
    int c = threadIdx.x;
    if (c >= C) return;
    float S = g_sum[layer*128 + c], Q = g_sq[layer*128 + c];
    float m = S * (1.f/524288.f);
    float var = Q * (1.f/524288.f) - m*m;
    float A = gamma[c] * rsqrtf(var + 1e-5f);
    g_a[layer*128 + c]  = A;
    g_bb[layer*128 + c] = beta[c] - m*A;
}

// ---------------- final: BN+ReLU of group-max, transposed store ----------------
__global__ void gfin_kernel(const float* __restrict__ gmax,
                            const float* __restrict__ A,
                            const float* __restrict__ B,
                            float* __restrict__ out) {
    __shared__ float t[32][33];
    int s0 = blockIdx.x*32, c0 = blockIdx.y*32, b = blockIdx.z;
    int tx = threadIdx.x, ty = threadIdx.y;
    for (int k = ty; k < 32; k += 8)
        t[k][tx] = gmax[(size_t)(b*1024 + s0 + k)*128 + c0 + tx];
    __syncthreads();
    for (int k = ty; k < 32; k += 8) {
        int c = c0 + k;
        float v = fmaxf(fmaf(t[tx][k], A[c], B[c]), 0.f);
        out[16*3*1024 + ((size_t)(b*128 + c))*1024 + s0 + tx] = v;
    }
}

// ---------------- launch ----------------
extern "C" void kernel_launch(void* const* d_in, const int* in_sizes, int n_in,
                              void* d_out, int out_size) {
    const float* xyz = (const float*)d_in[0];
    const float* pts = (const float*)d_in[1];
    const float* W0 = (const float*)d_in[2];
    const float* b0 = (const float*)d_in[3];
    const float* ga0 = (const float*)d_in[4];
    const float* be0 = (const float*)d_in[5];
    const float* W1 = (const float*)d_in[6];
    const float* b1 = (const float*)d_in[7];
    const float* ga1 = (const float*)d_in[8];
    const float* be1 = (const float*)d_in[9];
    const float* W2 = (const float*)d_in[10];
    const float* b2 = (const float*)d_in[11];
    const float* ga2 = (const float*)d_in[12];
    const float* be2 = (const float*)d_in[13];
    float* out = (float*)d_out;

    float *pY1, *pY2, *pGM, *pA, *pB, *pS, *pQ;
    uint32_t *pW2h, *pW2l, *pW3h, *pW3l;
    cudaGetSymbolAddress((void**)&pY1, g_Y1);
    cudaGetSymbolAddress((void**)&pY2, g_Y2);
    cudaGetSymbolAddress((void**)&pGM, g_gmax);
    cudaGetSymbolAddress((void**)&pA, g_a);
    cudaGetSymbolAddress((void**)&pB, g_bb);
    cudaGetSymbolAddress((void**)&pS, g_sum);
    cudaGetSymbolAddress((void**)&pQ, g_sq);
    cudaGetSymbolAddress((void**)&pW2h, g_W2h);
    cudaGetSymbolAddress((void**)&pW2l, g_W2l);
    cudaGetSymbolAddress((void**)&pW3h, g_W3h);
    cudaGetSymbolAddress((void**)&pW3l, g_W3l);

    const int smem1 = (2*128*44 + 2*64*44)*4 + 64*3*4;      // 68352
    const int smem2 = (256*36 + 2*64*36)*4  + 64*3*4;       // 56064
    const int smem3 = (256*36 + 2*128*36)*4 + 128*3*4;      // 75264
    cudaFuncSetAttribute(mlp1_mma_kernel, cudaFuncAttributeMaxDynamicSharedMemorySize, smem1);
    cudaFuncSetAttribute(mlp2_mma_kernel, cudaFuncAttributeMaxDynamicSharedMemorySize, smem2);
    cudaFuncSetAttribute(mlp3_mma_kernel, cudaFuncAttributeMaxDynamicSharedMemorySize, smem3);

    wprep_kernel<<<16, 256>>>(W0, W1, W2);
    transpose_kernel<<<dim3(Nx/32, Dx/32, Bx), dim3(32, 32)>>>(pts);
    fps_kernel<<<Bx, 256>>>(xyz, out);      // also zeroes stats
    qb_kernel<<<Bx*Sx/8, 256>>>(xyz);

    mlp1_mma_kernel<<<Px/128, 256, smem1>>>(xyz, b0, pY1, pS + 0, pQ + 0);
    finalize_kernel<<<1, 128>>>(0, ga0, be0, 64);

    mlp2_mma_kernel<<<Px/128, 256, smem2>>>(pY1, pW2h, pW2l, b1, pA + 0, pB + 0,
                                            pY2, pS + 128, pQ + 128);
    finalize_kernel<<<1, 128>>>(1, ga1, be1, 64);

    mlp3_mma_kernel<<<Px/128, 256, smem3>>>(pY2, pW3h, pW3l, b2, pA + 128, pB + 128,
                                            pGM, pS + 256, pQ + 256);
    finalize_kernel<<<1, 128>>>(2, ga2, be2, 128);

    gfin_kernel<<<dim3(32, 4, 16), dim3(32, 8)>>>(pGM, pA + 256, pB + 256, out);
}